// round 4
// baseline (speedup 1.0000x reference)
#include <cuda_runtime.h>
#include <cuda_bf16.h>
#include <cstdint>

// ---------------------------------------------------------------------------
// GPT-1 forward: B=4, S=1024, D=768, H=12, HD=64, N_LAYER=5
// Round 4: swizzled fragment-major smem (vector LDS), 64-row flash tiles.
// ---------------------------------------------------------------------------

#define NB 4
#define SS 1024
#define DD 768
#define HH 12
#define HDD 64
#define NLAYER 5
#define TOKENS (NB * SS)           // 4096
#define D3 (3 * DD)                // 2304
#define D4 (4 * DD)                // 3072

// -------------------- device scratch (no cudaMalloc allowed) ---------------
__device__ float g_h[TOKENS * DD];
__device__ float g_n[TOKENS * DD];
__device__ float g_tmp[TOKENS * DD];
__device__ float g_attn[TOKENS * DD];
__device__ float g_qkv[TOKENS * D3];
__device__ float g_fc[TOKENS * D4];
__device__ int   g_is_i64;

// -------------------- helpers ----------------------------------------------
__device__ __forceinline__ float warp_sum(float v) {
    #pragma unroll
    for (int o = 16; o; o >>= 1) v += __shfl_xor_sync(0xffffffffu, v, o);
    return v;
}
__device__ __forceinline__ float gelu_f(float x) {
    const float c2 = 1.5957691216057308f;  // 2*sqrt(2/pi)
    float u = c2 * (x + 0.044715f * x * x * x);
    return x / (1.0f + __expf(-u));
}
__device__ __forceinline__ uint32_t to_tf32(float x) {
    uint32_t u;
    asm("cvt.rna.tf32.f32 %0, %1;" : "=r"(u) : "f"(x));
    return u;
}
__device__ __forceinline__ float to_tf32f(float x) {
    return __uint_as_float(to_tf32(x));
}
__device__ __forceinline__ void mma8(float* c, const uint32_t* a, const uint32_t* b) {
    asm volatile(
        "mma.sync.aligned.m16n8k8.row.col.f32.tf32.tf32.f32 "
        "{%0,%1,%2,%3},{%4,%5,%6,%7},{%8,%9},{%0,%1,%2,%3};\n"
        : "+f"(c[0]), "+f"(c[1]), "+f"(c[2]), "+f"(c[3])
        : "r"(a[0]), "r"(a[1]), "r"(a[2]), "r"(a[3]), "r"(b[0]), "r"(b[1]));
}

// -------------------- input_ids dtype detection ----------------------------
__global__ void detect_kernel(const int* __restrict__ ids) {
    int any = 0;
    for (int i = 1; i < 64; i += 2) any |= ids[i];
    g_is_i64 = (any == 0) ? 1 : 0;
}

// -------------------- embedding --------------------------------------------
__global__ void embed_kernel(const int* __restrict__ ids,
                             const float* __restrict__ tok,
                             const float* __restrict__ pos,
                             float* __restrict__ h) {
    int i = blockIdx.x * blockDim.x + threadIdx.x;
    if (i >= TOKENS * DD) return;
    int t = i / DD;
    int d = i - t * DD;
    int s = t & (SS - 1);
    int id = g_is_i64 ? ids[2 * t] : ids[t];
    h[i] = tok[(size_t)id * DD + d] + pos[(size_t)s * DD + d];
}

// ---------------------------------------------------------------------------
// Dense tf32 GEMM (NN), fragment-major swizzled smem.
//   A smem column index: (m&15)*(BM/16) + (m>>4)  -> float4/float2 frag loads
//   B smem column index: (n&7)*(BN/8)  + (n>>3)   -> float4 frag loads
// MODE 0: +bias.  MODE 1: gelu(+bias).
// ---------------------------------------------------------------------------
template<int BM, int BN, int WM, int WN, int MODE>
__global__ __launch_bounds__(256)
void mma_gemm(const float* __restrict__ A, int lda,
              const float* __restrict__ B, int ldb,
              const float* __restrict__ bias,
              float* __restrict__ C, int ldc,
              int K) {
    constexpr int BK = 16;
    constexpr int WARPS_N = BN / WN;
    constexpr int AM = WM / 16;
    constexpr int AN = WN / 8;
    constexpr int NA  = (BM * BK) / (4 * 256);
    constexpr int NBt = (BN * BK) / (4 * 256);
    constexpr int BMS = BM + 4;
    constexpr int BNS = BN + 4;
    static_assert(AN == 4, "B frag float4 path expects AN==4");

    __shared__ float As[2][BK][BMS];
    __shared__ float Bs[2][BK][BNS];

    const int tid  = threadIdx.x;
    const int wid  = tid >> 5;
    const int lane = tid & 31;
    const int g    = lane >> 2;
    const int tg   = lane & 3;
    const int warpM = (wid / WARPS_N) * WM;
    const int warpN = (wid % WARPS_N) * WN;
    const int wm16  = warpM / 16;
    const int wn8   = warpN / 8;
    const int rowBase = blockIdx.y * BM;
    const int colBase = blockIdx.x * BN;

    float acc[AM][AN][4];
    #pragma unroll
    for (int i = 0; i < AM; i++)
        #pragma unroll
        for (int j = 0; j < AN; j++)
            #pragma unroll
            for (int q = 0; q < 4; q++) acc[i][j][q] = 0.0f;

    float4 aS[NA];
    float4 bS[NBt];

    auto stageT = [&](int kt) {
        int k0 = kt * BK;
        #pragma unroll
        for (int it = 0; it < NA; it++) {
            int idx = tid + it * 256;
            int r = idx >> 2, kq = idx & 3;
            aS[it] = *reinterpret_cast<const float4*>(
                A + (size_t)(rowBase + r) * lda + k0 + kq * 4);
        }
        #pragma unroll
        for (int it = 0; it < NBt; it++) {
            int idx = tid + it * 256;
            constexpr int BPR = BN / 4;
            int kr = idx / BPR, nq = idx % BPR;
            bS[it] = *reinterpret_cast<const float4*>(
                B + (size_t)(k0 + kr) * ldb + colBase + nq * 4);
        }
    };

    auto commitT = [&](int bw) {
        #pragma unroll
        for (int it = 0; it < NA; it++) {
            int idx = tid + it * 256;
            int r = idx >> 2, kq = idx & 3;
            int mc = (r & 15) * (BM / 16) + (r >> 4);
            const float* v = reinterpret_cast<const float*>(&aS[it]);
            #pragma unroll
            for (int c = 0; c < 4; c++) As[bw][kq * 4 + c][mc] = to_tf32f(v[c]);
        }
        #pragma unroll
        for (int it = 0; it < NBt; it++) {
            int idx = tid + it * 256;
            const float* v = reinterpret_cast<const float*>(&bS[it]);
            constexpr int BPR = BN / 4;
            int kr = idx / BPR, nq = idx % BPR;
            #pragma unroll
            for (int c = 0; c < 4; c++) {
                int n = nq * 4 + c;
                Bs[bw][kr][(n & 7) * (BN / 8) + (n >> 3)] = to_tf32f(v[c]);
            }
        }
    };

    stageT(0);
    commitT(0);
    __syncthreads();

    int buf = 0;
    const int KT = K / BK;
    for (int kt = 0; kt < KT; kt++) {
        bool more = (kt + 1 < KT);
        if (more) stageT(kt + 1);

        #pragma unroll
        for (int kk = 0; kk < BK; kk += 8) {
            uint32_t af[AM][4];
            if constexpr (AM == 4) {
                float q0[4], q1[4], q2[4], q3[4];
                *(float4*)q0 = *(const float4*)&As[buf][kk + tg][g * (BM/16) + wm16];
                *(float4*)q1 = *(const float4*)&As[buf][kk + tg][(g + 8) * (BM/16) + wm16];
                *(float4*)q2 = *(const float4*)&As[buf][kk + tg + 4][g * (BM/16) + wm16];
                *(float4*)q3 = *(const float4*)&As[buf][kk + tg + 4][(g + 8) * (BM/16) + wm16];
                #pragma unroll
                for (int i = 0; i < 4; i++) {
                    af[i][0] = __float_as_uint(q0[i]);
                    af[i][1] = __float_as_uint(q1[i]);
                    af[i][2] = __float_as_uint(q2[i]);
                    af[i][3] = __float_as_uint(q3[i]);
                }
            } else {
                float q0[2], q1[2], q2[2], q3[2];
                *(float2*)q0 = *(const float2*)&As[buf][kk + tg][g * (BM/16) + wm16];
                *(float2*)q1 = *(const float2*)&As[buf][kk + tg][(g + 8) * (BM/16) + wm16];
                *(float2*)q2 = *(const float2*)&As[buf][kk + tg + 4][g * (BM/16) + wm16];
                *(float2*)q3 = *(const float2*)&As[buf][kk + tg + 4][(g + 8) * (BM/16) + wm16];
                #pragma unroll
                for (int i = 0; i < AM; i++) {
                    af[i][0] = __float_as_uint(q0[i]);
                    af[i][1] = __float_as_uint(q1[i]);
                    af[i][2] = __float_as_uint(q2[i]);
                    af[i][3] = __float_as_uint(q3[i]);
                }
            }
            float b0[4], b1[4];
            *(float4*)b0 = *(const float4*)&Bs[buf][kk + tg][g * (BN/8) + wn8];
            *(float4*)b1 = *(const float4*)&Bs[buf][kk + tg + 4][g * (BN/8) + wn8];
            uint32_t bf[4][2];
            #pragma unroll
            for (int j = 0; j < 4; j++) {
                bf[j][0] = __float_as_uint(b0[j]);
                bf[j][1] = __float_as_uint(b1[j]);
            }
            #pragma unroll
            for (int i = 0; i < AM; i++)
                #pragma unroll
                for (int j = 0; j < 4; j++)
                    mma8(acc[i][j], af[i], bf[j]);
        }

        if (more) {
            commitT(buf ^ 1);
            __syncthreads();
        }
        buf ^= 1;
    }

    #pragma unroll
    for (int i = 0; i < AM; i++) {
        int r0 = rowBase + warpM + i * 16 + g;
        int r1 = r0 + 8;
        #pragma unroll
        for (int j = 0; j < AN; j++) {
            int c = colBase + warpN + j * 8 + tg * 2;
            float bb0 = bias[c], bb1 = bias[c + 1];
            float v0 = acc[i][j][0] + bb0, v1 = acc[i][j][1] + bb1;
            float v2 = acc[i][j][2] + bb0, v3 = acc[i][j][3] + bb1;
            if (MODE == 1) {
                v0 = gelu_f(v0); v1 = gelu_f(v1);
                v2 = gelu_f(v2); v3 = gelu_f(v3);
            }
            *reinterpret_cast<float2*>(C + (size_t)r0 * ldc + c) = make_float2(v0, v1);
            *reinterpret_cast<float2*>(C + (size_t)r1 * ldc + c) = make_float2(v2, v3);
        }
    }
}

// ---------------------------------------------------------------------------
// Fused flash attention, 64 q-rows per block, 4 warps (16 rows each, AM=1).
// K smem: [d][t'] with t' = (t&7)*8 + (t>>3)   (float4 frag loads)
// V smem: [t][d'] with d' = (d&7)*8 + (d>>3)   (float4 frag loads)
// Q smem: [d][m] plain (scalar frag loads; AM=1).
// ---------------------------------------------------------------------------
#define FSTR 68

__global__ __launch_bounds__(128)
void flash_kernel(const float* __restrict__ qkv,
                  const float* __restrict__ mask,
                  float* __restrict__ attn) {
    extern __shared__ float sm[];
    float* Qs  = sm;                        // [64][68]
    float* Ks  = Qs + 64 * FSTR;            // [64 d][68 t']
    float* Vs  = Ks + 64 * FSTR;            // [64 t][68 d']
    float* Ems = Vs + 64 * FSTR;            // [64]

    const int tid  = threadIdx.x;
    const int wid  = tid >> 5;
    const int lane = tid & 31;
    const int g    = lane >> 2;
    const int tg   = lane & 3;
    const int warpM = wid * 16;
    const int qBase = blockIdx.x * 64;
    const int bh = blockIdx.y;
    const int b = bh / HH, h = bh - b * HH;

    const float* Qg = qkv + (size_t)b * SS * D3 + h * HDD;
    const float* Kg = Qg + DD;
    const float* Vg = Qg + 2 * DD;

    // ---- load Q tile (64x64) -> Qs[d][m], tf32 ----
    #pragma unroll
    for (int i = 0; i < 8; i++) {
        int idx = i * 128 + tid;
        int r = idx >> 4, dq = idx & 15;
        float4 v = *reinterpret_cast<const float4*>(
            Qg + (size_t)(qBase + r) * D3 + dq * 4);
        Qs[(dq * 4 + 0) * FSTR + r] = to_tf32f(v.x);
        Qs[(dq * 4 + 1) * FSTR + r] = to_tf32f(v.y);
        Qs[(dq * 4 + 2) * FSTR + r] = to_tf32f(v.z);
        Qs[(dq * 4 + 3) * FSTR + r] = to_tf32f(v.w);
    }

    float o[8][4];
    #pragma unroll
    for (int j = 0; j < 8; j++)
        #pragma unroll
        for (int q = 0; q < 4; q++) o[j][q] = 0.0f;
    float mrow0 = -1e30f, mrow1 = -1e30f;
    float lrow0 = 0.f, lrow1 = 0.f;

    const int row0 = qBase + warpM + g;
    const int row1 = row0 + 8;
    const int srcA = (lane & 28) | (tg >> 1);
    const int srcB = srcA | 2;
    const int e1   = tg & 1;

    const int nkb = blockIdx.x + 1;
    for (int kb = 0; kb < nkb; kb++) {
        __syncthreads();
        // ---- load K[t][d] -> Ks[d][t'], V[t][d] -> Vs[t][d'], tf32 ----
        #pragma unroll
        for (int i = 0; i < 8; i++) {
            int idx = i * 128 + tid;
            int kt = idx >> 4, dq = idx & 15;
            int tsw = (kt & 7) * 8 + (kt >> 3);
            float4 kv = *reinterpret_cast<const float4*>(
                Kg + (size_t)(kb * 64 + kt) * D3 + dq * 4);
            Ks[(dq * 4 + 0) * FSTR + tsw] = to_tf32f(kv.x);
            Ks[(dq * 4 + 1) * FSTR + tsw] = to_tf32f(kv.y);
            Ks[(dq * 4 + 2) * FSTR + tsw] = to_tf32f(kv.z);
            Ks[(dq * 4 + 3) * FSTR + tsw] = to_tf32f(kv.w);
            float4 vv = *reinterpret_cast<const float4*>(
                Vg + (size_t)(kb * 64 + kt) * D3 + dq * 4);
            const float vals[4] = {vv.x, vv.y, vv.z, vv.w};
            #pragma unroll
            for (int c = 0; c < 4; c++) {
                int d = dq * 4 + c;
                Vs[kt * FSTR + (d & 7) * 8 + (d >> 3)] = to_tf32f(vals[c]);
            }
        }
        if (tid < 64)
            Ems[tid] = (1.0f - mask[b * SS + kb * 64 + tid]) * (-3.402823466e38f);
        __syncthreads();

        // ---- S = Q @ K^T (16x64 per warp) ----
        float s[8][4];
        #pragma unroll
        for (int j = 0; j < 8; j++)
            #pragma unroll
            for (int q = 0; q < 4; q++) s[j][q] = 0.0f;

        #pragma unroll
        for (int kk = 0; kk < 8; kk++) {
            int kr = kk * 8;
            uint32_t af[4];
            af[0] = __float_as_uint(Qs[(kr + tg) * FSTR + warpM + g]);
            af[1] = __float_as_uint(Qs[(kr + tg) * FSTR + warpM + g + 8]);
            af[2] = __float_as_uint(Qs[(kr + tg + 4) * FSTR + warpM + g]);
            af[3] = __float_as_uint(Qs[(kr + tg + 4) * FSTR + warpM + g + 8]);
            float kA[8], kB[8];
            *(float4*)&kA[0] = *(const float4*)&Ks[(kr + tg) * FSTR + g * 8];
            *(float4*)&kA[4] = *(const float4*)&Ks[(kr + tg) * FSTR + g * 8 + 4];
            *(float4*)&kB[0] = *(const float4*)&Ks[(kr + tg + 4) * FSTR + g * 8];
            *(float4*)&kB[4] = *(const float4*)&Ks[(kr + tg + 4) * FSTR + g * 8 + 4];
            #pragma unroll
            for (int j = 0; j < 8; j++) {
                uint32_t bf[2] = {__float_as_uint(kA[j]), __float_as_uint(kB[j])};
                mma8(s[j], af, bf);
            }
        }

        // ---- scale + causal + ext mask, online softmax ----
        float mx0 = -1e30f, mx1 = -1e30f;
        #pragma unroll
        for (int j = 0; j < 8; j++) {
            int c0 = kb * 64 + j * 8 + tg * 2;
            float em0 = Ems[j * 8 + tg * 2];
            float em1 = Ems[j * 8 + tg * 2 + 1];
            float v0 = s[j][0] * 0.125f;
            float v1 = s[j][1] * 0.125f;
            float v2 = s[j][2] * 0.125f;
            float v3 = s[j][3] * 0.125f;
            if (c0 > row0)     v0 = -1e4f;
            if (c0 + 1 > row0) v1 = -1e4f;
            if (c0 > row1)     v2 = -1e4f;
            if (c0 + 1 > row1) v3 = -1e4f;
            v0 += em0; v1 += em1; v2 += em0; v3 += em1;
            s[j][0] = v0; s[j][1] = v1; s[j][2] = v2; s[j][3] = v3;
            mx0 = fmaxf(mx0, fmaxf(v0, v1));
            mx1 = fmaxf(mx1, fmaxf(v2, v3));
        }
        mx0 = fmaxf(mx0, __shfl_xor_sync(0xffffffffu, mx0, 1));
        mx0 = fmaxf(mx0, __shfl_xor_sync(0xffffffffu, mx0, 2));
        mx1 = fmaxf(mx1, __shfl_xor_sync(0xffffffffu, mx1, 1));
        mx1 = fmaxf(mx1, __shfl_xor_sync(0xffffffffu, mx1, 2));

        float mn0 = fmaxf(mrow0, mx0);
        float mn1 = fmaxf(mrow1, mx1);
        float al0 = __expf(mrow0 - mn0);
        float al1 = __expf(mrow1 - mn1);
        mrow0 = mn0; mrow1 = mn1;

        float sum0 = 0.f, sum1 = 0.f;
        #pragma unroll
        for (int j = 0; j < 8; j++) {
            float p0 = __expf(s[j][0] - mn0);
            float p1 = __expf(s[j][1] - mn0);
            float p2 = __expf(s[j][2] - mn1);
            float p3 = __expf(s[j][3] - mn1);
            s[j][0] = p0; s[j][1] = p1; s[j][2] = p2; s[j][3] = p3;
            sum0 += p0 + p1; sum1 += p2 + p3;
        }
        sum0 += __shfl_xor_sync(0xffffffffu, sum0, 1);
        sum0 += __shfl_xor_sync(0xffffffffu, sum0, 2);
        sum1 += __shfl_xor_sync(0xffffffffu, sum1, 1);
        sum1 += __shfl_xor_sync(0xffffffffu, sum1, 2);
        lrow0 = lrow0 * al0 + sum0;
        lrow1 = lrow1 * al1 + sum1;

        #pragma unroll
        for (int jo = 0; jo < 8; jo++) {
            o[jo][0] *= al0; o[jo][1] *= al0;
            o[jo][2] *= al1; o[jo][3] *= al1;
        }

        // ---- O += P @ V : C-frag -> A-frag via intra-quad shuffles ----
        #pragma unroll
        for (int j = 0; j < 8; j++) {
            float x0A = __shfl_sync(0xffffffffu, s[j][0], srcA);
            float x1A = __shfl_sync(0xffffffffu, s[j][1], srcA);
            float x0B = __shfl_sync(0xffffffffu, s[j][0], srcB);
            float x1B = __shfl_sync(0xffffffffu, s[j][1], srcB);
            float y0A = __shfl_sync(0xffffffffu, s[j][2], srcA);
            float y1A = __shfl_sync(0xffffffffu, s[j][3], srcA);
            float y0B = __shfl_sync(0xffffffffu, s[j][2], srcB);
            float y1B = __shfl_sync(0xffffffffu, s[j][3], srcB);
            uint32_t pa[4];
            pa[0] = to_tf32(e1 ? x1A : x0A);
            pa[1] = to_tf32(e1 ? y1A : y0A);
            pa[2] = to_tf32(e1 ? x1B : x0B);
            pa[3] = to_tf32(e1 ? y1B : y0B);

            float vA[8], vB[8];
            *(float4*)&vA[0] = *(const float4*)&Vs[(j * 8 + tg) * FSTR + g * 8];
            *(float4*)&vA[4] = *(const float4*)&Vs[(j * 8 + tg) * FSTR + g * 8 + 4];
            *(float4*)&vB[0] = *(const float4*)&Vs[(j * 8 + tg + 4) * FSTR + g * 8];
            *(float4*)&vB[4] = *(const float4*)&Vs[(j * 8 + tg + 4) * FSTR + g * 8 + 4];
            #pragma unroll
            for (int jo = 0; jo < 8; jo++) {
                uint32_t bf[2] = {__float_as_uint(vA[jo]), __float_as_uint(vB[jo])};
                mma8(o[jo], pa, bf);
            }
        }
    }

    // ---- normalize and write out ----
    float inv0 = 1.0f / lrow0;
    float inv1 = 1.0f / lrow1;
    #pragma unroll
    for (int jo = 0; jo < 8; jo++) {
        int col = h * HDD + jo * 8 + tg * 2;
        *reinterpret_cast<float2*>(attn + (size_t)(b * SS + row0) * DD + col) =
            make_float2(o[jo][0] * inv0, o[jo][1] * inv0);
        *reinterpret_cast<float2*>(attn + (size_t)(b * SS + row1) * DD + col) =
            make_float2(o[jo][2] * inv1, o[jo][3] * inv1);
    }
}

// -------------------- fused residual-add + LayerNorm -----------------------
__global__ void add_ln_kernel(const float* __restrict__ x,
                              const float* __restrict__ y,
                              const float* __restrict__ w,
                              const float* __restrict__ b,
                              float* __restrict__ out) {
    int row = blockIdx.x;
    const float* xr = x + (size_t)row * DD;
    const float* yr = y + (size_t)row * DD;
    int tid = threadIdx.x;

    float v0 = xr[tid] + yr[tid];
    float v1 = xr[tid + 256] + yr[tid + 256];
    float v2 = xr[tid + 512] + yr[tid + 512];

    __shared__ float sh[8];
    float s = warp_sum(v0 + v1 + v2);
    if ((tid & 31) == 0) sh[tid >> 5] = s;
    __syncthreads();
    float tot = 0.f;
    #pragma unroll
    for (int i = 0; i < 8; i++) tot += sh[i];
    float mu = tot * (1.0f / DD);
    __syncthreads();

    float d0 = v0 - mu, d1 = v1 - mu, d2 = v2 - mu;
    float s2 = warp_sum(d0 * d0 + d1 * d1 + d2 * d2);
    if ((tid & 31) == 0) sh[tid >> 5] = s2;
    __syncthreads();
    float tot2 = 0.f;
    #pragma unroll
    for (int i = 0; i < 8; i++) tot2 += sh[i];
    float r = rsqrtf(tot2 * (1.0f / DD) + 1e-5f);

    float* orow = out + (size_t)row * DD;
    orow[tid]       = d0 * r * w[tid]       + b[tid];
    orow[tid + 256] = d1 * r * w[tid + 256] + b[tid + 256];
    orow[tid + 512] = d2 * r * w[tid + 512] + b[tid + 512];
}

// ---------------------------------------------------------------------------
extern "C" void kernel_launch(void* const* d_in, const int* in_sizes, int n_in,
                              void* d_out, int out_size) {
    const int*   ids      = (const int*)  d_in[0];
    const float* mask     = (const float*)d_in[2];
    const float* tok_emb  = (const float*)d_in[3];
    const float* pos_emb  = (const float*)d_in[4];
    const float* c_attn_w = (const float*)d_in[5];
    const float* c_attn_b = (const float*)d_in[6];
    const float* c_proj_w = (const float*)d_in[7];
    const float* c_proj_b = (const float*)d_in[8];
    const float* ln1_w    = (const float*)d_in[9];
    const float* ln1_b    = (const float*)d_in[10];
    const float* c_fc_w   = (const float*)d_in[11];
    const float* c_fc_b   = (const float*)d_in[12];
    const float* mlp_w    = (const float*)d_in[13];
    const float* mlp_b    = (const float*)d_in[14];
    const float* ln2_w    = (const float*)d_in[15];
    const float* ln2_b    = (const float*)d_in[16];

    float *h, *n, *tmp, *attn, *qkv, *fc;
    cudaGetSymbolAddress((void**)&h,    g_h);
    cudaGetSymbolAddress((void**)&n,    g_n);
    cudaGetSymbolAddress((void**)&tmp,  g_tmp);
    cudaGetSymbolAddress((void**)&attn, g_attn);
    cudaGetSymbolAddress((void**)&qkv,  g_qkv);
    cudaGetSymbolAddress((void**)&fc,   g_fc);

    const int flashSmem = (3 * 64 * FSTR + 64) * 4;  // 52480 B
    static int s_attr_set = 0;
    if (!s_attr_set) {
        cudaFuncSetAttribute(flash_kernel,
                             cudaFuncAttributeMaxDynamicSharedMemorySize,
                             flashSmem);
        s_attr_set = 1;
    }

    detect_kernel<<<1, 1>>>(ids);
    embed_kernel<<<(TOKENS * DD + 255) / 256, 256>>>(ids, tok_emb, pos_emb, h);

    for (int i = 0; i < NLAYER; i++) {
        // QKV: [4096,768] @ [768,2304]
        mma_gemm<128, 128, 64, 32, 0><<<dim3(D3 / 128, TOKENS / 128), 256>>>(
            h, DD, c_attn_w + (size_t)i * DD * D3, D3,
            c_attn_b + (size_t)i * D3, qkv, D3, DD);

        // fused flash attention -> attn [4096,768]
        flash_kernel<<<dim3(SS / 64, NB * HH), 128, flashSmem>>>(qkv, mask, attn);

        // attn out projection: [4096,768] @ [768,768]  (BM=64 -> 384 CTAs)
        mma_gemm<64, 128, 32, 32, 0><<<dim3(DD / 128, TOKENS / 64), 256>>>(
            attn, DD, c_proj_w + (size_t)i * DD * DD, DD,
            c_proj_b + (size_t)i * DD, tmp, DD, DD);

        // n = LN(h + attn_proj)
        add_ln_kernel<<<TOKENS, 256>>>(h, tmp, ln1_w + i * DD, ln1_b + i * DD, n);

        // fc = gelu(n @ c_fc_w + b): [4096,768] @ [768,3072]
        mma_gemm<128, 128, 64, 32, 1><<<dim3(D4 / 128, TOKENS / 128), 256>>>(
            n, DD, c_fc_w + (size_t)i * DD * D4, D4,
            c_fc_b + (size_t)i * D4, fc, D4, DD);

        // m = fc @ mlp_w + b: [4096,3072] @ [3072,768]  (BM=64 -> 384 CTAs)
        mma_gemm<64, 128, 32, 32, 0><<<dim3(DD / 128, TOKENS / 64), 256>>>(
            fc, D4, mlp_w + (size_t)i * D4 * DD, DD,
            mlp_b + (size_t)i * DD, tmp, DD, D4);

        // h = LN(n + m)  (last layer writes straight to d_out)
        float* dst = (i == NLAYER - 1) ? (float*)d_out : h;
        add_ln_kernel<<<TOKENS, 256>>>(n, tmp, ln2_w + i * DD, ln2_b + i * DD, dst);
    }
}

// round 5
// speedup vs baseline: 1.6763x; 1.6763x over previous
#include <cuda_runtime.h>
#include <cuda_bf16.h>
#include <cstdint>

// ---------------------------------------------------------------------------
// GPT-1 forward: B=4, S=1024, D=768, H=12, HD=64, N_LAYER=5
// Round 5: R3 baseline + ldmatrix-based dense GEMMs (conflict-audited).
// ---------------------------------------------------------------------------

#define NB 4
#define SS 1024
#define DD 768
#define HH 12
#define HDD 64
#define NLAYER 5
#define TOKENS (NB * SS)           // 4096
#define D3 (3 * DD)                // 2304
#define D4 (4 * DD)                // 3072

// -------------------- device scratch (no cudaMalloc allowed) ---------------
__device__ float g_h[TOKENS * DD];
__device__ float g_n[TOKENS * DD];
__device__ float g_tmp[TOKENS * DD];
__device__ float g_attn[TOKENS * DD];
__device__ float g_qkv[TOKENS * D3];
__device__ float g_fc[TOKENS * D4];
__device__ int   g_is_i64;

// -------------------- helpers ----------------------------------------------
__device__ __forceinline__ float warp_sum(float v) {
    #pragma unroll
    for (int o = 16; o; o >>= 1) v += __shfl_xor_sync(0xffffffffu, v, o);
    return v;
}
__device__ __forceinline__ float gelu_f(float x) {
    const float c2 = 1.5957691216057308f;  // 2*sqrt(2/pi); 0.5x(1+tanh(u)) == x*sigmoid(2u)
    float u = c2 * (x + 0.044715f * x * x * x);
    return x / (1.0f + __expf(-u));
}
__device__ __forceinline__ uint32_t to_tf32(float x) {
    uint32_t u;
    asm("cvt.rna.tf32.f32 %0, %1;" : "=r"(u) : "f"(x));
    return u;
}
__device__ __forceinline__ float to_tf32f(float x) {
    return __uint_as_float(to_tf32(x));
}
__device__ __forceinline__ void mma8(float* c, const uint32_t* a, const uint32_t* b) {
    asm volatile(
        "mma.sync.aligned.m16n8k8.row.col.f32.tf32.tf32.f32 "
        "{%0,%1,%2,%3},{%4,%5,%6,%7},{%8,%9},{%0,%1,%2,%3};\n"
        : "+f"(c[0]), "+f"(c[1]), "+f"(c[2]), "+f"(c[3])
        : "r"(a[0]), "r"(a[1]), "r"(a[2]), "r"(a[3]), "r"(b[0]), "r"(b[1]));
}
__device__ __forceinline__ void ldsm4(uint32_t* r, uint32_t addr) {
    asm volatile("ldmatrix.sync.aligned.m8n8.x4.shared.b16 {%0,%1,%2,%3}, [%4];"
                 : "=r"(r[0]), "=r"(r[1]), "=r"(r[2]), "=r"(r[3]) : "r"(addr));
}

// -------------------- input_ids dtype detection ----------------------------
__global__ void detect_kernel(const int* __restrict__ ids) {
    int any = 0;
    for (int i = 1; i < 64; i += 2) any |= ids[i];
    g_is_i64 = (any == 0) ? 1 : 0;
}

// -------------------- embedding --------------------------------------------
__global__ void embed_kernel(const int* __restrict__ ids,
                             const float* __restrict__ tok,
                             const float* __restrict__ pos,
                             float* __restrict__ h) {
    int i = blockIdx.x * blockDim.x + threadIdx.x;
    if (i >= TOKENS * DD) return;
    int t = i / DD;
    int d = i - t * DD;
    int s = t & (SS - 1);
    int id = g_is_i64 ? ids[2 * t] : ids[t];
    h[i] = tok[(size_t)id * DD + d] + pos[(size_t)s * DD + d];
}

// ---------------------------------------------------------------------------
// Dense tf32 GEMM (NN), 128x128x16 tiles, 8 warps of 64x32.
// Smem: As[m][20] (k-contiguous rows), Bs[n][20] (k-contiguous rows).
// Fragments via ldmatrix.m8n8.x4 (conflict-free: 20-word row stride).
// MODE 0: +bias.  MODE 1: gelu(+bias).
// ---------------------------------------------------------------------------
template<int MODE>
__global__ __launch_bounds__(256, 2)
void mma_gemm(const float* __restrict__ A, int lda,
              const float* __restrict__ B, int ldb,
              const float* __restrict__ bias,
              float* __restrict__ C, int ldc,
              int K) {
    constexpr int BM = 128, BN = 128, BK = 16;

    __shared__ float As[2][BM][20];
    __shared__ float Bs[2][BN][20];

    const int tid  = threadIdx.x;
    const int wid  = tid >> 5;
    const int lane = tid & 31;
    const int g    = lane >> 2;
    const int tg   = lane & 3;
    const int warpM = (wid >> 2) * 64;   // 2 warp-rows
    const int warpN = (wid & 3) * 32;    // 4 warp-cols
    const int rowBase = blockIdx.y * BM;
    const int colBase = blockIdx.x * BN;

    // ldmatrix lane address offsets (bytes)
    //  A: mats = {rows 0-7,k | rows 8-15,k | rows 0-7,k+4 | rows 8-15,k+4}
    const uint32_t aLaneOff = ((lane & 15) * 20 + ((lane & 16) ? 4 : 0)) * 4;
    //  B: mats = {n 0-7,k | n 0-7,k+4 | n 8-15,k | n 8-15,k+4}
    const uint32_t bLaneOff = ((((lane & 7) | ((lane & 16) >> 1))) * 20 +
                               ((lane & 8) ? 4 : 0)) * 4;
    const uint32_t aSm = (uint32_t)__cvta_generic_to_shared(&As[0][0][0]);
    const uint32_t bSm = (uint32_t)__cvta_generic_to_shared(&Bs[0][0][0]);
    constexpr uint32_t STG = BM * 20 * 4;   // bytes per stage

    float acc[4][4][4];
    #pragma unroll
    for (int i = 0; i < 4; i++)
        #pragma unroll
        for (int j = 0; j < 4; j++)
            #pragma unroll
            for (int q = 0; q < 4; q++) acc[i][j][q] = 0.0f;

    float4 aS[2];
    float  bS[2][4];

    auto stageT = [&](int kt) {
        int k0 = kt * BK;
        #pragma unroll
        for (int it = 0; it < 2; it++) {
            int idx = tid + it * 256;
            int r = idx >> 2, kq = idx & 3;
            aS[it] = *reinterpret_cast<const float4*>(
                A + (size_t)(rowBase + r) * lda + k0 + kq * 4);
        }
        #pragma unroll
        for (int it = 0; it < 2; it++) {
            int idx = tid + it * 256;
            int n = idx & 127, k4 = idx >> 7;
            #pragma unroll
            for (int j = 0; j < 4; j++)
                bS[it][j] = B[(size_t)(k0 + k4 * 4 + j) * ldb + colBase + n];
        }
    };

    auto commitT = [&](int bw) {
        #pragma unroll
        for (int it = 0; it < 2; it++) {
            int idx = tid + it * 256;
            int r = idx >> 2, kq = idx & 3;
            float4 v = aS[it];
            float4 w = make_float4(to_tf32f(v.x), to_tf32f(v.y),
                                   to_tf32f(v.z), to_tf32f(v.w));
            *reinterpret_cast<float4*>(&As[bw][r][kq * 4]) = w;
        }
        #pragma unroll
        for (int it = 0; it < 2; it++) {
            int idx = tid + it * 256;
            int n = idx & 127, k4 = idx >> 7;
            float4 w = make_float4(to_tf32f(bS[it][0]), to_tf32f(bS[it][1]),
                                   to_tf32f(bS[it][2]), to_tf32f(bS[it][3]));
            *reinterpret_cast<float4*>(&Bs[bw][n][k4 * 4]) = w;
        }
    };

    stageT(0);
    commitT(0);
    __syncthreads();

    int buf = 0;
    const int KT = K / BK;
    for (int kt = 0; kt < KT; kt++) {
        bool more = (kt + 1 < KT);
        if (more) stageT(kt + 1);

        #pragma unroll
        for (int kk = 0; kk < BK; kk += 8) {
            uint32_t aAddr = aSm + buf * STG + aLaneOff + (warpM * 20 + kk) * 4;
            uint32_t bAddr = bSm + buf * STG + bLaneOff + (warpN * 20 + kk) * 4;
            uint32_t af[4][4];
            #pragma unroll
            for (int i = 0; i < 4; i++)
                ldsm4(af[i], aAddr + i * (16 * 20 * 4));
            uint32_t bf[4][2];
            {
                uint32_t t[4];
                ldsm4(t, bAddr);
                bf[0][0] = t[0]; bf[0][1] = t[1];
                bf[1][0] = t[2]; bf[1][1] = t[3];
                ldsm4(t, bAddr + 16 * 20 * 4);
                bf[2][0] = t[0]; bf[2][1] = t[1];
                bf[3][0] = t[2]; bf[3][1] = t[3];
            }
            #pragma unroll
            for (int i = 0; i < 4; i++)
                #pragma unroll
                for (int j = 0; j < 4; j++)
                    mma8(acc[i][j], af[i], bf[j]);
        }

        if (more) {
            commitT(buf ^ 1);
            __syncthreads();
        }
        buf ^= 1;
    }

    #pragma unroll
    for (int i = 0; i < 4; i++) {
        int r0 = rowBase + warpM + i * 16 + g;
        int r1 = r0 + 8;
        #pragma unroll
        for (int j = 0; j < 4; j++) {
            int c = colBase + warpN + j * 8 + tg * 2;
            float bb0 = bias[c], bb1 = bias[c + 1];
            float v0 = acc[i][j][0] + bb0, v1 = acc[i][j][1] + bb1;
            float v2 = acc[i][j][2] + bb0, v3 = acc[i][j][3] + bb1;
            if (MODE == 1) {
                v0 = gelu_f(v0); v1 = gelu_f(v1);
                v2 = gelu_f(v2); v3 = gelu_f(v3);
            }
            *reinterpret_cast<float2*>(C + (size_t)r0 * ldc + c) = make_float2(v0, v1);
            *reinterpret_cast<float2*>(C + (size_t)r1 * ldc + c) = make_float2(v2, v3);
        }
    }
}

// ---------------------------------------------------------------------------
// Fused flash attention (R3 version, 128 q-rows per block, 4 warps).
// ---------------------------------------------------------------------------
#define QSTR 132   // Qs row stride (128+4)
#define KSTR 68    // Ks/Vs row stride (64+4)

__global__ __launch_bounds__(128)
void flash_kernel(const float* __restrict__ qkv,
                  const float* __restrict__ mask,
                  float* __restrict__ attn) {
    extern __shared__ float sm[];
    float* Qs  = sm;                        // [64 d][132 m] tf32
    float* Ks  = Qs + 64 * QSTR;            // [64 d][68 t]  tf32
    float* Vs  = Ks + 64 * KSTR;            // [64 t][68 d]  tf32
    float* Ems = Vs + 64 * KSTR;            // [64]

    const int tid  = threadIdx.x;
    const int wid  = tid >> 5;
    const int lane = tid & 31;
    const int g    = lane >> 2;
    const int tg   = lane & 3;
    const int warpM = wid * 32;
    const int qBase = blockIdx.x * 128;
    const int bh = blockIdx.y;
    const int b = bh / HH, h = bh - b * HH;

    const float* Qg = qkv + (size_t)b * SS * D3 + h * HDD;
    const float* Kg = Qg + DD;
    const float* Vg = Qg + 2 * DD;

    // ---- load Q tile (128x64) -> Qs[d][r], tf32 ----
    #pragma unroll
    for (int i = 0; i < 16; i++) {
        int idx = i * 128 + tid;
        int r = idx >> 4, dq = idx & 15;
        float4 v = *reinterpret_cast<const float4*>(
            Qg + (size_t)(qBase + r) * D3 + dq * 4);
        Qs[(dq * 4 + 0) * QSTR + r] = to_tf32f(v.x);
        Qs[(dq * 4 + 1) * QSTR + r] = to_tf32f(v.y);
        Qs[(dq * 4 + 2) * QSTR + r] = to_tf32f(v.z);
        Qs[(dq * 4 + 3) * QSTR + r] = to_tf32f(v.w);
    }

    float o[2][8][4];
    #pragma unroll
    for (int i = 0; i < 2; i++)
        #pragma unroll
        for (int j = 0; j < 8; j++)
            #pragma unroll
            for (int q = 0; q < 4; q++) o[i][j][q] = 0.0f;
    float mrow[2][2] = {{-1e30f, -1e30f}, {-1e30f, -1e30f}};
    float lrow[2][2] = {{0.f, 0.f}, {0.f, 0.f}};

    const int row[2][2] = {{qBase + warpM + g,      qBase + warpM + g + 8},
                           {qBase + warpM + 16 + g, qBase + warpM + 24 + g}};
    const int srcA = (lane & 28) | (tg >> 1);
    const int srcB = srcA | 2;
    const int e1   = tg & 1;

    const int nkb = qBase / 64 + 2;
    for (int kb = 0; kb < nkb; kb++) {
        __syncthreads();
        #pragma unroll
        for (int i = 0; i < 8; i++) {
            int idx = i * 128 + tid;
            int kt = idx >> 4, dq = idx & 15;
            float4 kv = *reinterpret_cast<const float4*>(
                Kg + (size_t)(kb * 64 + kt) * D3 + dq * 4);
            Ks[(dq * 4 + 0) * KSTR + kt] = to_tf32f(kv.x);
            Ks[(dq * 4 + 1) * KSTR + kt] = to_tf32f(kv.y);
            Ks[(dq * 4 + 2) * KSTR + kt] = to_tf32f(kv.z);
            Ks[(dq * 4 + 3) * KSTR + kt] = to_tf32f(kv.w);
            float4 vv = *reinterpret_cast<const float4*>(
                Vg + (size_t)(kb * 64 + kt) * D3 + dq * 4);
            Vs[kt * KSTR + dq * 4 + 0] = to_tf32f(vv.x);
            Vs[kt * KSTR + dq * 4 + 1] = to_tf32f(vv.y);
            Vs[kt * KSTR + dq * 4 + 2] = to_tf32f(vv.z);
            Vs[kt * KSTR + dq * 4 + 3] = to_tf32f(vv.w);
        }
        if (tid < 64)
            Ems[tid] = (1.0f - mask[b * SS + kb * 64 + tid]) * (-3.402823466e38f);
        __syncthreads();

        // ---- S = Q @ K^T ----
        float s[2][8][4];
        #pragma unroll
        for (int i = 0; i < 2; i++)
            #pragma unroll
            for (int j = 0; j < 8; j++)
                #pragma unroll
                for (int q = 0; q < 4; q++) s[i][j][q] = 0.0f;

        #pragma unroll
        for (int kk = 0; kk < 8; kk++) {
            int kr = kk * 8;
            uint32_t af[2][4];
            #pragma unroll
            for (int i = 0; i < 2; i++) {
                int m = warpM + i * 16 + g;
                af[i][0] = __float_as_uint(Qs[(kr + tg) * QSTR + m]);
                af[i][1] = __float_as_uint(Qs[(kr + tg) * QSTR + m + 8]);
                af[i][2] = __float_as_uint(Qs[(kr + tg + 4) * QSTR + m]);
                af[i][3] = __float_as_uint(Qs[(kr + tg + 4) * QSTR + m + 8]);
            }
            #pragma unroll
            for (int j = 0; j < 8; j++) {
                uint32_t bf[2];
                bf[0] = __float_as_uint(Ks[(kr + tg) * KSTR + j * 8 + g]);
                bf[1] = __float_as_uint(Ks[(kr + tg + 4) * KSTR + j * 8 + g]);
                mma8(s[0][j], af[0], bf);
                mma8(s[1][j], af[1], bf);
            }
        }

        // ---- scale + causal + ext mask, online softmax ----
        #pragma unroll
        for (int i = 0; i < 2; i++) {
            float mx0 = -1e30f, mx1 = -1e30f;
            #pragma unroll
            for (int j = 0; j < 8; j++) {
                int c0 = kb * 64 + j * 8 + tg * 2;
                float em0 = Ems[j * 8 + tg * 2];
                float em1 = Ems[j * 8 + tg * 2 + 1];
                float v0 = s[i][j][0] * 0.125f;
                float v1 = s[i][j][1] * 0.125f;
                float v2 = s[i][j][2] * 0.125f;
                float v3 = s[i][j][3] * 0.125f;
                if (c0 > row[i][0])     v0 = -1e4f;
                if (c0 + 1 > row[i][0]) v1 = -1e4f;
                if (c0 > row[i][1])     v2 = -1e4f;
                if (c0 + 1 > row[i][1]) v3 = -1e4f;
                v0 += em0; v1 += em1; v2 += em0; v3 += em1;
                s[i][j][0] = v0; s[i][j][1] = v1;
                s[i][j][2] = v2; s[i][j][3] = v3;
                mx0 = fmaxf(mx0, fmaxf(v0, v1));
                mx1 = fmaxf(mx1, fmaxf(v2, v3));
            }
            mx0 = fmaxf(mx0, __shfl_xor_sync(0xffffffffu, mx0, 1));
            mx0 = fmaxf(mx0, __shfl_xor_sync(0xffffffffu, mx0, 2));
            mx1 = fmaxf(mx1, __shfl_xor_sync(0xffffffffu, mx1, 1));
            mx1 = fmaxf(mx1, __shfl_xor_sync(0xffffffffu, mx1, 2));

            float mn0 = fmaxf(mrow[i][0], mx0);
            float mn1 = fmaxf(mrow[i][1], mx1);
            float al0 = __expf(mrow[i][0] - mn0);
            float al1 = __expf(mrow[i][1] - mn1);
            mrow[i][0] = mn0; mrow[i][1] = mn1;

            float sum0 = 0.f, sum1 = 0.f;
            #pragma unroll
            for (int j = 0; j < 8; j++) {
                float p0 = __expf(s[i][j][0] - mn0);
                float p1 = __expf(s[i][j][1] - mn0);
                float p2 = __expf(s[i][j][2] - mn1);
                float p3 = __expf(s[i][j][3] - mn1);
                s[i][j][0] = p0; s[i][j][1] = p1;
                s[i][j][2] = p2; s[i][j][3] = p3;
                sum0 += p0 + p1; sum1 += p2 + p3;
            }
            sum0 += __shfl_xor_sync(0xffffffffu, sum0, 1);
            sum0 += __shfl_xor_sync(0xffffffffu, sum0, 2);
            sum1 += __shfl_xor_sync(0xffffffffu, sum1, 1);
            sum1 += __shfl_xor_sync(0xffffffffu, sum1, 2);
            lrow[i][0] = lrow[i][0] * al0 + sum0;
            lrow[i][1] = lrow[i][1] * al1 + sum1;

            #pragma unroll
            for (int jo = 0; jo < 8; jo++) {
                o[i][jo][0] *= al0; o[i][jo][1] *= al0;
                o[i][jo][2] *= al1; o[i][jo][3] *= al1;
            }
        }

        // ---- O += P @ V ----
        #pragma unroll
        for (int j = 0; j < 8; j++) {
            uint32_t pa[2][4];
            #pragma unroll
            for (int i = 0; i < 2; i++) {
                float x0A = __shfl_sync(0xffffffffu, s[i][j][0], srcA);
                float x1A = __shfl_sync(0xffffffffu, s[i][j][1], srcA);
                float x0B = __shfl_sync(0xffffffffu, s[i][j][0], srcB);
                float x1B = __shfl_sync(0xffffffffu, s[i][j][1], srcB);
                float y0A = __shfl_sync(0xffffffffu, s[i][j][2], srcA);
                float y1A = __shfl_sync(0xffffffffu, s[i][j][3], srcA);
                float y0B = __shfl_sync(0xffffffffu, s[i][j][2], srcB);
                float y1B = __shfl_sync(0xffffffffu, s[i][j][3], srcB);
                pa[i][0] = to_tf32(e1 ? x1A : x0A);
                pa[i][1] = to_tf32(e1 ? y1A : y0A);
                pa[i][2] = to_tf32(e1 ? x1B : x0B);
                pa[i][3] = to_tf32(e1 ? y1B : y0B);
            }
            #pragma unroll
            for (int jo = 0; jo < 8; jo++) {
                uint32_t bf[2];
                bf[0] = __float_as_uint(Vs[(j * 8 + tg) * KSTR + jo * 8 + g]);
                bf[1] = __float_as_uint(Vs[(j * 8 + tg + 4) * KSTR + jo * 8 + g]);
                mma8(o[0][jo], pa[0], bf);
                mma8(o[1][jo], pa[1], bf);
            }
        }
    }

    // ---- normalize and write out ----
    #pragma unroll
    for (int i = 0; i < 2; i++) {
        float inv0 = 1.0f / lrow[i][0];
        float inv1 = 1.0f / lrow[i][1];
        #pragma unroll
        for (int jo = 0; jo < 8; jo++) {
            int col = h * HDD + jo * 8 + tg * 2;
            *reinterpret_cast<float2*>(
                attn + (size_t)(b * SS + row[i][0]) * DD + col) =
                make_float2(o[i][jo][0] * inv0, o[i][jo][1] * inv0);
            *reinterpret_cast<float2*>(
                attn + (size_t)(b * SS + row[i][1]) * DD + col) =
                make_float2(o[i][jo][2] * inv1, o[i][jo][3] * inv1);
        }
    }
}

// -------------------- fused residual-add + LayerNorm -----------------------
__global__ void add_ln_kernel(const float* __restrict__ x,
                              const float* __restrict__ y,
                              const float* __restrict__ w,
                              const float* __restrict__ b,
                              float* __restrict__ out) {
    int row = blockIdx.x;
    const float* xr = x + (size_t)row * DD;
    const float* yr = y + (size_t)row * DD;
    int tid = threadIdx.x;

    float v0 = xr[tid] + yr[tid];
    float v1 = xr[tid + 256] + yr[tid + 256];
    float v2 = xr[tid + 512] + yr[tid + 512];

    __shared__ float sh[8];
    float s = warp_sum(v0 + v1 + v2);
    if ((tid & 31) == 0) sh[tid >> 5] = s;
    __syncthreads();
    float tot = 0.f;
    #pragma unroll
    for (int i = 0; i < 8; i++) tot += sh[i];
    float mu = tot * (1.0f / DD);
    __syncthreads();

    float d0 = v0 - mu, d1 = v1 - mu, d2 = v2 - mu;
    float s2 = warp_sum(d0 * d0 + d1 * d1 + d2 * d2);
    if ((tid & 31) == 0) sh[tid >> 5] = s2;
    __syncthreads();
    float tot2 = 0.f;
    #pragma unroll
    for (int i = 0; i < 8; i++) tot2 += sh[i];
    float r = rsqrtf(tot2 * (1.0f / DD) + 1e-5f);

    float* orow = out + (size_t)row * DD;
    orow[tid]       = d0 * r * w[tid]       + b[tid];
    orow[tid + 256] = d1 * r * w[tid + 256] + b[tid + 256];
    orow[tid + 512] = d2 * r * w[tid + 512] + b[tid + 512];
}

// ---------------------------------------------------------------------------
extern "C" void kernel_launch(void* const* d_in, const int* in_sizes, int n_in,
                              void* d_out, int out_size) {
    const int*   ids      = (const int*)  d_in[0];
    const float* mask     = (const float*)d_in[2];
    const float* tok_emb  = (const float*)d_in[3];
    const float* pos_emb  = (const float*)d_in[4];
    const float* c_attn_w = (const float*)d_in[5];
    const float* c_attn_b = (const float*)d_in[6];
    const float* c_proj_w = (const float*)d_in[7];
    const float* c_proj_b = (const float*)d_in[8];
    const float* ln1_w    = (const float*)d_in[9];
    const float* ln1_b    = (const float*)d_in[10];
    const float* c_fc_w   = (const float*)d_in[11];
    const float* c_fc_b   = (const float*)d_in[12];
    const float* mlp_w    = (const float*)d_in[13];
    const float* mlp_b    = (const float*)d_in[14];
    const float* ln2_w    = (const float*)d_in[15];
    const float* ln2_b    = (const float*)d_in[16];

    float *h, *n, *tmp, *attn, *qkv, *fc;
    cudaGetSymbolAddress((void**)&h,    g_h);
    cudaGetSymbolAddress((void**)&n,    g_n);
    cudaGetSymbolAddress((void**)&tmp,  g_tmp);
    cudaGetSymbolAddress((void**)&attn, g_attn);
    cudaGetSymbolAddress((void**)&qkv,  g_qkv);
    cudaGetSymbolAddress((void**)&fc,   g_fc);

    const int flashSmem = (64 * QSTR + 2 * 64 * KSTR + 64) * 4;  // 68864 B
    static int s_attr_set = 0;
    if (!s_attr_set) {
        cudaFuncSetAttribute(flash_kernel,
                             cudaFuncAttributeMaxDynamicSharedMemorySize,
                             flashSmem);
        s_attr_set = 1;
    }

    detect_kernel<<<1, 1>>>(ids);
    embed_kernel<<<(TOKENS * DD + 255) / 256, 256>>>(ids, tok_emb, pos_emb, h);

    for (int i = 0; i < NLAYER; i++) {
        // QKV: [4096,768] @ [768,2304]
        mma_gemm<0><<<dim3(D3 / 128, TOKENS / 128), 256>>>(
            h, DD, c_attn_w + (size_t)i * DD * D3, D3,
            c_attn_b + (size_t)i * D3, qkv, D3, DD);

        // fused flash attention -> attn [4096,768]
        flash_kernel<<<dim3(SS / 128, NB * HH), 128, flashSmem>>>(qkv, mask, attn);

        // attn out projection: [4096,768] @ [768,768]
        mma_gemm<0><<<dim3(DD / 128, TOKENS / 128), 256>>>(
            attn, DD, c_proj_w + (size_t)i * DD * DD, DD,
            c_proj_b + (size_t)i * DD, tmp, DD, DD);

        // n = LN(h + attn_proj)
        add_ln_kernel<<<TOKENS, 256>>>(h, tmp, ln1_w + i * DD, ln1_b + i * DD, n);

        // fc = gelu(n @ c_fc_w + b): [4096,768] @ [768,3072]
        mma_gemm<1><<<dim3(D4 / 128, TOKENS / 128), 256>>>(
            n, DD, c_fc_w + (size_t)i * DD * D4, D4,
            c_fc_b + (size_t)i * D4, fc, D4, DD);

        // m = fc @ mlp_w + b: [4096,3072] @ [3072,768]
        mma_gemm<0><<<dim3(DD / 128, TOKENS / 128), 256>>>(
            fc, D4, mlp_w + (size_t)i * D4 * DD, DD,
            mlp_b + (size_t)i * DD, tmp, DD, D4);

        // h = LN(n + m)  (last layer writes straight to d_out)
        float* dst = (i == NLAYER - 1) ? (float*)d_out : h;
        add_ln_kernel<<<TOKENS, 256>>>(n, tmp, ln2_w + i * DD, ln2_b + i * DD, dst);
    }
}

// round 7
// speedup vs baseline: 1.7837x; 1.0641x over previous
#include <cuda_runtime.h>
#include <cuda_bf16.h>
#include <cstdint>

// ---------------------------------------------------------------------------
// GPT-1 forward: B=4, S=1024, D=768, H=12, HD=64, N_LAYER=5
// Round 7 (= R6 resubmit after infra failure): cp.async 3-stage GEMM pipeline
// on pre-transposed tf32 weights; flash with 8 warps + ldmatrix Q/K.
// ---------------------------------------------------------------------------

#define NB 4
#define SS 1024
#define DD 768
#define HH 12
#define HDD 64
#define NLAYER 5
#define TOKENS (NB * SS)           // 4096
#define D3 (3 * DD)                // 2304
#define D4 (4 * DD)                // 3072

// -------------------- device scratch (no cudaMalloc allowed) ---------------
__device__ __align__(128) float g_h[TOKENS * DD];
__device__ __align__(128) float g_hr[TOKENS * DD];
__device__ __align__(128) float g_n[TOKENS * DD];
__device__ __align__(128) float g_nr[TOKENS * DD];
__device__ __align__(128) float g_tmp[TOKENS * DD];
__device__ __align__(128) float g_attn[TOKENS * DD];
__device__ __align__(128) float g_qkv[TOKENS * D3];
__device__ __align__(128) float g_fc[TOKENS * D4];
__device__ __align__(128) float g_wta[NLAYER * DD * D3];
__device__ __align__(128) float g_wtp[NLAYER * DD * DD];
__device__ __align__(128) float g_wtf[NLAYER * DD * D4];
__device__ __align__(128) float g_wtm[NLAYER * D4 * DD];
__device__ int g_is_i64;

// -------------------- helpers ----------------------------------------------
__device__ __forceinline__ float warp_sum(float v) {
    #pragma unroll
    for (int o = 16; o; o >>= 1) v += __shfl_xor_sync(0xffffffffu, v, o);
    return v;
}
__device__ __forceinline__ float gelu_f(float x) {
    const float c2 = 1.5957691216057308f;  // 2*sqrt(2/pi)
    float u = c2 * (x + 0.044715f * x * x * x);
    return x / (1.0f + __expf(-u));
}
__device__ __forceinline__ uint32_t to_tf32(float x) {
    uint32_t u;
    asm("cvt.rna.tf32.f32 %0, %1;" : "=r"(u) : "f"(x));
    return u;
}
__device__ __forceinline__ float to_tf32f(float x) {
    return __uint_as_float(to_tf32(x));
}
__device__ __forceinline__ void mma8(float* c, const uint32_t* a, const uint32_t* b) {
    asm volatile(
        "mma.sync.aligned.m16n8k8.row.col.f32.tf32.tf32.f32 "
        "{%0,%1,%2,%3},{%4,%5,%6,%7},{%8,%9},{%0,%1,%2,%3};\n"
        : "+f"(c[0]), "+f"(c[1]), "+f"(c[2]), "+f"(c[3])
        : "r"(a[0]), "r"(a[1]), "r"(a[2]), "r"(a[3]), "r"(b[0]), "r"(b[1]));
}
__device__ __forceinline__ void ldsm4(uint32_t* r, uint32_t addr) {
    asm volatile("ldmatrix.sync.aligned.m8n8.x4.shared.b16 {%0,%1,%2,%3}, [%4];"
                 : "=r"(r[0]), "=r"(r[1]), "=r"(r[2]), "=r"(r[3]) : "r"(addr));
}
__device__ __forceinline__ void cpasync16(uint32_t dst, const float* src) {
    asm volatile("cp.async.cg.shared.global [%0], [%1], 16;" :: "r"(dst), "l"(src));
}

// -------------------- input_ids dtype detection ----------------------------
__global__ void detect_kernel(const int* __restrict__ ids) {
    int any = 0;
    for (int i = 1; i < 64; i += 2) any |= ids[i];
    g_is_i64 = (any == 0) ? 1 : 0;
}

// -------------------- embedding (dual write: fp32 + tf32-rounded) ----------
__global__ void embed_kernel(const int* __restrict__ ids,
                             const float* __restrict__ tok,
                             const float* __restrict__ pos,
                             float* __restrict__ h,
                             float* __restrict__ hr) {
    int i = blockIdx.x * blockDim.x + threadIdx.x;
    if (i >= TOKENS * DD) return;
    int t = i / DD;
    int d = i - t * DD;
    int s = t & (SS - 1);
    int id = g_is_i64 ? ids[2 * t] : ids[t];
    float v = tok[(size_t)id * DD + d] + pos[(size_t)s * DD + d];
    h[i] = v;
    hr[i] = to_tf32f(v);
}

// -------------------- weight transpose + rna round: [K][N] -> [N][K] -------
__global__ void transpose_w(const float* __restrict__ src,
                            float* __restrict__ dst, int K, int N) {
    __shared__ float t[32][33];
    int n0 = blockIdx.x * 32, k0 = blockIdx.y * 32;
    size_t off = (size_t)blockIdx.z * K * N;
    int tx = threadIdx.x, ty = threadIdx.y;
    #pragma unroll
    for (int i = 0; i < 4; i++)
        t[ty + i * 8][tx] = src[off + (size_t)(k0 + ty + i * 8) * N + n0 + tx];
    __syncthreads();
    #pragma unroll
    for (int i = 0; i < 4; i++)
        dst[off + (size_t)(n0 + ty + i * 8) * K + k0 + tx] =
            to_tf32f(t[tx][ty + i * 8]);
}

// ---------------------------------------------------------------------------
// cp.async 3-stage tf32 GEMM.  A [M][K] pre-rounded, Bt [N][K] pre-rounded.
// 128x128x16 tiles, 8 warps of 64x32, ldmatrix frags from [r][20] smem.
// MODE 0: +bias.  MODE 1: rna(gelu(+bias)).
// ---------------------------------------------------------------------------
template<int MODE>
__global__ __launch_bounds__(256, 2)
void gemm3(const float* __restrict__ A,
           const float* __restrict__ Bt,
           const float* __restrict__ bias,
           float* __restrict__ C, int ldc,
           int K) {
    constexpr int BM = 128, BN = 128, BK = 16;
    constexpr int SW = BM * 20;              // words per operand stage

    extern __shared__ float dyn[];
    float* AsBase = dyn;                      // 3 stages A
    float* BsBase = dyn + 3 * SW;             // 3 stages B

    const int tid  = threadIdx.x;
    const int wid  = tid >> 5;
    const int lane = tid & 31;
    const int g    = lane >> 2;
    const int tg   = lane & 3;
    const int warpM = (wid >> 2) * 64;
    const int warpN = (wid & 3) * 32;
    const int rowBase = blockIdx.y * BM;
    const int colBase = blockIdx.x * BN;

    const uint32_t aSm = (uint32_t)__cvta_generic_to_shared(AsBase);
    const uint32_t bSm = (uint32_t)__cvta_generic_to_shared(BsBase);
    const uint32_t aLaneOff = ((lane & 15) * 20 + ((lane & 16) ? 4 : 0)) * 4;
    const uint32_t bLaneOff = ((((lane & 7) | ((lane & 16) >> 1))) * 20 +
                               ((lane & 8) ? 4 : 0)) * 4;

    const int r  = tid >> 2;        // 0..63 (+64 for second batch)
    const int kq = tid & 3;

    float acc[4][4][4];
    #pragma unroll
    for (int i = 0; i < 4; i++)
        #pragma unroll
        for (int j = 0; j < 4; j++)
            #pragma unroll
            for (int q = 0; q < 4; q++) acc[i][j][q] = 0.0f;

    auto stage = [&](int kt, int buf) {
        int k0 = kt * BK;
        uint32_t aB = aSm + buf * SW * 4;
        uint32_t bB = bSm + buf * SW * 4;
        #pragma unroll
        for (int it = 0; it < 2; it++) {
            int rr = r + it * 64;
            cpasync16(aB + (rr * 20 + kq * 4) * 4,
                      A + (size_t)(rowBase + rr) * K + k0 + kq * 4);
        }
        #pragma unroll
        for (int it = 0; it < 2; it++) {
            int nn = r + it * 64;
            cpasync16(bB + (nn * 20 + kq * 4) * 4,
                      Bt + (size_t)(colBase + nn) * K + k0 + kq * 4);
        }
        asm volatile("cp.async.commit_group;");
    };

    const int KT = K / BK;
    stage(0, 0);
    stage(1, 1);

    for (int kt = 0; kt < KT; kt++) {
        asm volatile("cp.async.wait_group 1;");
        __syncthreads();
        if (kt + 2 < KT) stage(kt + 2, (kt + 2) % 3);

        int buf = kt % 3;
        uint32_t aBase = aSm + buf * SW * 4 + aLaneOff + (warpM * 20) * 4;
        uint32_t bBase = bSm + buf * SW * 4 + bLaneOff + (warpN * 20) * 4;
        #pragma unroll
        for (int kk = 0; kk < BK; kk += 8) {
            uint32_t af[4][4];
            #pragma unroll
            for (int i = 0; i < 4; i++)
                ldsm4(af[i], aBase + kk * 4 + i * (16 * 20 * 4));
            uint32_t bf[4][2];
            {
                uint32_t t[4];
                ldsm4(t, bBase + kk * 4);
                bf[0][0] = t[0]; bf[0][1] = t[1];
                bf[1][0] = t[2]; bf[1][1] = t[3];
                ldsm4(t, bBase + kk * 4 + 16 * 20 * 4);
                bf[2][0] = t[0]; bf[2][1] = t[1];
                bf[3][0] = t[2]; bf[3][1] = t[3];
            }
            #pragma unroll
            for (int i = 0; i < 4; i++)
                #pragma unroll
                for (int j = 0; j < 4; j++)
                    mma8(acc[i][j], af[i], bf[j]);
        }
        __syncthreads();
    }

    #pragma unroll
    for (int i = 0; i < 4; i++) {
        int r0 = rowBase + warpM + i * 16 + g;
        int r1 = r0 + 8;
        #pragma unroll
        for (int j = 0; j < 4; j++) {
            int c = colBase + warpN + j * 8 + tg * 2;
            float bb0 = bias[c], bb1 = bias[c + 1];
            float v0 = acc[i][j][0] + bb0, v1 = acc[i][j][1] + bb1;
            float v2 = acc[i][j][2] + bb0, v3 = acc[i][j][3] + bb1;
            if (MODE == 1) {
                v0 = to_tf32f(gelu_f(v0)); v1 = to_tf32f(gelu_f(v1));
                v2 = to_tf32f(gelu_f(v2)); v3 = to_tf32f(gelu_f(v3));
            }
            *reinterpret_cast<float2*>(C + (size_t)r0 * ldc + c) = make_float2(v0, v1);
            *reinterpret_cast<float2*>(C + (size_t)r1 * ldc + c) = make_float2(v2, v3);
        }
    }
}

// ---------------------------------------------------------------------------
// Fused flash attention: 128 q-rows/CTA, 8 warps (16 rows each),
// ldmatrix Q & K frags, scalar V frags, output tf32-rounded.
// ---------------------------------------------------------------------------
#define FS 68

__global__ __launch_bounds__(256)
void flash_kernel(const float* __restrict__ qkv,
                  const float* __restrict__ mask,
                  float* __restrict__ attn) {
    extern __shared__ float sm[];
    float* Qs  = sm;               // [128 m][68 d]
    float* Ks  = Qs + 128 * FS;    // [64 t][68 d]
    float* Vs  = Ks + 64 * FS;     // [64 t][68 d]
    float* Ems = Vs + 64 * FS;     // [64]

    const int tid  = threadIdx.x;
    const int wid  = tid >> 5;
    const int lane = tid & 31;
    const int g    = lane >> 2;
    const int tg   = lane & 3;
    const int qBase = blockIdx.x * 128;
    const int bh = blockIdx.y;
    const int b = bh / HH, h = bh - b * HH;

    const float* Qg = qkv + (size_t)b * SS * D3 + h * HDD;
    const float* Kg = Qg + DD;
    const float* Vg = Qg + 2 * DD;

    // ---- Q tile (128x64) -> Qs[m][d], tf32 ----
    #pragma unroll
    for (int i = 0; i < 8; i++) {
        int idx = i * 256 + tid;
        int r = idx >> 4, dq = idx & 15;
        float4 v = *reinterpret_cast<const float4*>(
            Qg + (size_t)(qBase + r) * D3 + dq * 4);
        float4 w = make_float4(to_tf32f(v.x), to_tf32f(v.y),
                               to_tf32f(v.z), to_tf32f(v.w));
        *reinterpret_cast<float4*>(&Qs[r * FS + dq * 4]) = w;
    }

    float o[8][4];
    #pragma unroll
    for (int j = 0; j < 8; j++)
        #pragma unroll
        for (int q = 0; q < 4; q++) o[j][q] = 0.0f;
    float mrow0 = -1e30f, mrow1 = -1e30f;
    float lrow0 = 0.f, lrow1 = 0.f;

    const int row0 = qBase + wid * 16 + g;
    const int row1 = row0 + 8;
    const int srcA = (lane & 28) | (tg >> 1);
    const int srcB = srcA | 2;
    const int e1   = tg & 1;

    const uint32_t qSm = (uint32_t)__cvta_generic_to_shared(Qs);
    const uint32_t kSm = (uint32_t)__cvta_generic_to_shared(Ks);
    const uint32_t aOff = ((wid * 16 + (lane & 15)) * FS + ((lane & 16) ? 4 : 0)) * 4;
    const uint32_t bOff = ((((lane & 7) | ((lane & 16) >> 1))) * FS +
                           ((lane & 8) ? 4 : 0)) * 4;

    const int nkb = blockIdx.x * 2 + 2;
    for (int kb = 0; kb < nkb; kb++) {
        __syncthreads();
        #pragma unroll
        for (int i = 0; i < 4; i++) {
            int idx = i * 256 + tid;
            int kt = idx >> 4, dq = idx & 15;
            float4 kv = *reinterpret_cast<const float4*>(
                Kg + (size_t)(kb * 64 + kt) * D3 + dq * 4);
            *reinterpret_cast<float4*>(&Ks[kt * FS + dq * 4]) =
                make_float4(to_tf32f(kv.x), to_tf32f(kv.y),
                            to_tf32f(kv.z), to_tf32f(kv.w));
            float4 vv = *reinterpret_cast<const float4*>(
                Vg + (size_t)(kb * 64 + kt) * D3 + dq * 4);
            *reinterpret_cast<float4*>(&Vs[kt * FS + dq * 4]) =
                make_float4(to_tf32f(vv.x), to_tf32f(vv.y),
                            to_tf32f(vv.z), to_tf32f(vv.w));
        }
        if (tid < 64)
            Ems[tid] = (1.0f - mask[b * SS + kb * 64 + tid]) * (-3.402823466e38f);
        __syncthreads();

        // ---- S = Q @ K^T (16x64 per warp) ----
        float s[8][4];
        #pragma unroll
        for (int j = 0; j < 8; j++)
            #pragma unroll
            for (int q = 0; q < 4; q++) s[j][q] = 0.0f;

        #pragma unroll
        for (int kk = 0; kk < 8; kk++) {
            uint32_t af[4];
            ldsm4(af, qSm + aOff + kk * 8 * 4);
            uint32_t bf[8][2];
            #pragma unroll
            for (int m = 0; m < 4; m++) {
                uint32_t t4[4];
                ldsm4(t4, kSm + bOff + (m * 16 * FS + kk * 8) * 4);
                bf[2 * m][0] = t4[0]; bf[2 * m][1] = t4[1];
                bf[2 * m + 1][0] = t4[2]; bf[2 * m + 1][1] = t4[3];
            }
            #pragma unroll
            for (int j = 0; j < 8; j++)
                mma8(s[j], af, bf[j]);
        }

        // ---- scale + causal + ext mask, online softmax ----
        float mx0 = -1e30f, mx1 = -1e30f;
        #pragma unroll
        for (int j = 0; j < 8; j++) {
            int c0 = kb * 64 + j * 8 + tg * 2;
            float em0 = Ems[j * 8 + tg * 2];
            float em1 = Ems[j * 8 + tg * 2 + 1];
            float v0 = s[j][0] * 0.125f;
            float v1 = s[j][1] * 0.125f;
            float v2 = s[j][2] * 0.125f;
            float v3 = s[j][3] * 0.125f;
            if (c0 > row0)     v0 = -1e4f;
            if (c0 + 1 > row0) v1 = -1e4f;
            if (c0 > row1)     v2 = -1e4f;
            if (c0 + 1 > row1) v3 = -1e4f;
            v0 += em0; v1 += em1; v2 += em0; v3 += em1;
            s[j][0] = v0; s[j][1] = v1; s[j][2] = v2; s[j][3] = v3;
            mx0 = fmaxf(mx0, fmaxf(v0, v1));
            mx1 = fmaxf(mx1, fmaxf(v2, v3));
        }
        mx0 = fmaxf(mx0, __shfl_xor_sync(0xffffffffu, mx0, 1));
        mx0 = fmaxf(mx0, __shfl_xor_sync(0xffffffffu, mx0, 2));
        mx1 = fmaxf(mx1, __shfl_xor_sync(0xffffffffu, mx1, 1));
        mx1 = fmaxf(mx1, __shfl_xor_sync(0xffffffffu, mx1, 2));

        float mn0 = fmaxf(mrow0, mx0);
        float mn1 = fmaxf(mrow1, mx1);
        float al0 = __expf(mrow0 - mn0);
        float al1 = __expf(mrow1 - mn1);
        mrow0 = mn0; mrow1 = mn1;

        float sum0 = 0.f, sum1 = 0.f;
        #pragma unroll
        for (int j = 0; j < 8; j++) {
            float p0 = __expf(s[j][0] - mn0);
            float p1 = __expf(s[j][1] - mn0);
            float p2 = __expf(s[j][2] - mn1);
            float p3 = __expf(s[j][3] - mn1);
            s[j][0] = p0; s[j][1] = p1; s[j][2] = p2; s[j][3] = p3;
            sum0 += p0 + p1; sum1 += p2 + p3;
        }
        sum0 += __shfl_xor_sync(0xffffffffu, sum0, 1);
        sum0 += __shfl_xor_sync(0xffffffffu, sum0, 2);
        sum1 += __shfl_xor_sync(0xffffffffu, sum1, 1);
        sum1 += __shfl_xor_sync(0xffffffffu, sum1, 2);
        lrow0 = lrow0 * al0 + sum0;
        lrow1 = lrow1 * al1 + sum1;

        #pragma unroll
        for (int jo = 0; jo < 8; jo++) {
            o[jo][0] *= al0; o[jo][1] *= al0;
            o[jo][2] *= al1; o[jo][3] *= al1;
        }

        // ---- O += P @ V : C-frag -> A-frag via intra-quad shuffles ----
        #pragma unroll
        for (int j = 0; j < 8; j++) {
            float x0A = __shfl_sync(0xffffffffu, s[j][0], srcA);
            float x1A = __shfl_sync(0xffffffffu, s[j][1], srcA);
            float x0B = __shfl_sync(0xffffffffu, s[j][0], srcB);
            float x1B = __shfl_sync(0xffffffffu, s[j][1], srcB);
            float y0A = __shfl_sync(0xffffffffu, s[j][2], srcA);
            float y1A = __shfl_sync(0xffffffffu, s[j][3], srcA);
            float y0B = __shfl_sync(0xffffffffu, s[j][2], srcB);
            float y1B = __shfl_sync(0xffffffffu, s[j][3], srcB);
            uint32_t pa[4];
            pa[0] = to_tf32(e1 ? x1A : x0A);
            pa[1] = to_tf32(e1 ? y1A : y0A);
            pa[2] = to_tf32(e1 ? x1B : x0B);
            pa[3] = to_tf32(e1 ? y1B : y0B);
            #pragma unroll
            for (int jo = 0; jo < 8; jo++) {
                uint32_t bf[2];
                bf[0] = __float_as_uint(Vs[(j * 8 + tg) * FS + jo * 8 + g]);
                bf[1] = __float_as_uint(Vs[(j * 8 + tg + 4) * FS + jo * 8 + g]);
                mma8(o[jo], pa, bf);
            }
        }
    }

    // ---- normalize, round, write out ----
    float inv0 = 1.0f / lrow0;
    float inv1 = 1.0f / lrow1;
    #pragma unroll
    for (int jo = 0; jo < 8; jo++) {
        int col = h * HDD + jo * 8 + tg * 2;
        *reinterpret_cast<float2*>(attn + (size_t)(b * SS + row0) * DD + col) =
            make_float2(to_tf32f(o[jo][0] * inv0), to_tf32f(o[jo][1] * inv0));
        *reinterpret_cast<float2*>(attn + (size_t)(b * SS + row1) * DD + col) =
            make_float2(to_tf32f(o[jo][2] * inv1), to_tf32f(o[jo][3] * inv1));
    }
}

// -------------------- fused residual-add + LayerNorm (dual write) ----------
__global__ void add_ln_kernel(const float* __restrict__ x,
                              const float* __restrict__ y,
                              const float* __restrict__ w,
                              const float* __restrict__ b,
                              float* __restrict__ out,
                              float* __restrict__ out_r) {
    int row = blockIdx.x;
    const float* xr = x + (size_t)row * DD;
    const float* yr = y + (size_t)row * DD;
    int tid = threadIdx.x;

    float v0 = xr[tid] + yr[tid];
    float v1 = xr[tid + 256] + yr[tid + 256];
    float v2 = xr[tid + 512] + yr[tid + 512];

    __shared__ float sh[8];
    float s = warp_sum(v0 + v1 + v2);
    if ((tid & 31) == 0) sh[tid >> 5] = s;
    __syncthreads();
    float tot = 0.f;
    #pragma unroll
    for (int i = 0; i < 8; i++) tot += sh[i];
    float mu = tot * (1.0f / DD);
    __syncthreads();

    float d0 = v0 - mu, d1 = v1 - mu, d2 = v2 - mu;
    float s2 = warp_sum(d0 * d0 + d1 * d1 + d2 * d2);
    if ((tid & 31) == 0) sh[tid >> 5] = s2;
    __syncthreads();
    float tot2 = 0.f;
    #pragma unroll
    for (int i = 0; i < 8; i++) tot2 += sh[i];
    float r = rsqrtf(tot2 * (1.0f / DD) + 1e-5f);

    float o0 = d0 * r * w[tid]       + b[tid];
    float o1 = d1 * r * w[tid + 256] + b[tid + 256];
    float o2 = d2 * r * w[tid + 512] + b[tid + 512];
    float* orow = out + (size_t)row * DD;
    orow[tid] = o0; orow[tid + 256] = o1; orow[tid + 512] = o2;
    if (out_r) {
        float* rrow = out_r + (size_t)row * DD;
        rrow[tid]       = to_tf32f(o0);
        rrow[tid + 256] = to_tf32f(o1);
        rrow[tid + 512] = to_tf32f(o2);
    }
}

// ---------------------------------------------------------------------------
extern "C" void kernel_launch(void* const* d_in, const int* in_sizes, int n_in,
                              void* d_out, int out_size) {
    const int*   ids      = (const int*)  d_in[0];
    const float* mask     = (const float*)d_in[2];
    const float* tok_emb  = (const float*)d_in[3];
    const float* pos_emb  = (const float*)d_in[4];
    const float* c_attn_w = (const float*)d_in[5];
    const float* c_attn_b = (const float*)d_in[6];
    const float* c_proj_w = (const float*)d_in[7];
    const float* c_proj_b = (const float*)d_in[8];
    const float* ln1_w    = (const float*)d_in[9];
    const float* ln1_b    = (const float*)d_in[10];
    const float* c_fc_w   = (const float*)d_in[11];
    const float* c_fc_b   = (const float*)d_in[12];
    const float* mlp_w    = (const float*)d_in[13];
    const float* mlp_b    = (const float*)d_in[14];
    const float* ln2_w    = (const float*)d_in[15];
    const float* ln2_b    = (const float*)d_in[16];

    float *h, *hr, *n, *nr, *tmp, *attn, *qkv, *fc;
    float *wta, *wtp, *wtf, *wtm;
    cudaGetSymbolAddress((void**)&h,    g_h);
    cudaGetSymbolAddress((void**)&hr,   g_hr);
    cudaGetSymbolAddress((void**)&n,    g_n);
    cudaGetSymbolAddress((void**)&nr,   g_nr);
    cudaGetSymbolAddress((void**)&tmp,  g_tmp);
    cudaGetSymbolAddress((void**)&attn, g_attn);
    cudaGetSymbolAddress((void**)&qkv,  g_qkv);
    cudaGetSymbolAddress((void**)&fc,   g_fc);
    cudaGetSymbolAddress((void**)&wta,  g_wta);
    cudaGetSymbolAddress((void**)&wtp,  g_wtp);
    cudaGetSymbolAddress((void**)&wtf,  g_wtf);
    cudaGetSymbolAddress((void**)&wtm,  g_wtm);

    const int gemmSmem  = 3 * 2 * 128 * 20 * 4;                  // 61440 B
    const int flashSmem = (128 * FS + 2 * 64 * FS + 64) * 4;     // 69888 B
    static int s_attr_set = 0;
    if (!s_attr_set) {
        cudaFuncSetAttribute(gemm3<0>, cudaFuncAttributeMaxDynamicSharedMemorySize, gemmSmem);
        cudaFuncSetAttribute(gemm3<1>, cudaFuncAttributeMaxDynamicSharedMemorySize, gemmSmem);
        cudaFuncSetAttribute(flash_kernel, cudaFuncAttributeMaxDynamicSharedMemorySize, flashSmem);
        s_attr_set = 1;
    }

    detect_kernel<<<1, 1>>>(ids);
    embed_kernel<<<(TOKENS * DD + 255) / 256, 256>>>(ids, tok_emb, pos_emb, h, hr);

    // one-time weight transposes (tf32-rounded)
    dim3 tb(32, 8);
    transpose_w<<<dim3(D3 / 32, DD / 32, NLAYER), tb>>>(c_attn_w, wta, DD, D3);
    transpose_w<<<dim3(DD / 32, DD / 32, NLAYER), tb>>>(c_proj_w, wtp, DD, DD);
    transpose_w<<<dim3(D4 / 32, DD / 32, NLAYER), tb>>>(c_fc_w,   wtf, DD, D4);
    transpose_w<<<dim3(DD / 32, D4 / 32, NLAYER), tb>>>(mlp_w,    wtm, D4, DD);

    for (int i = 0; i < NLAYER; i++) {
        // QKV: hr [4096,768] @ Wt [2304,768]^T
        gemm3<0><<<dim3(D3 / 128, TOKENS / 128), 256, gemmSmem>>>(
            hr, wta + (size_t)i * DD * D3, c_attn_b + (size_t)i * D3,
            qkv, D3, DD);

        // fused flash attention -> attn (tf32-rounded)
        flash_kernel<<<dim3(SS / 128, NB * HH), 256, flashSmem>>>(qkv, mask, attn);

        // attn out projection
        gemm3<0><<<dim3(DD / 128, TOKENS / 128), 256, gemmSmem>>>(
            attn, wtp + (size_t)i * DD * DD, c_proj_b + (size_t)i * DD,
            tmp, DD, DD);

        // n = LN(h + attn_proj), nr = rna(n)
        add_ln_kernel<<<TOKENS, 256>>>(h, tmp, ln1_w + i * DD, ln1_b + i * DD, n, nr);

        // fc = rna(gelu(nr @ Wfc + b))
        gemm3<1><<<dim3(D4 / 128, TOKENS / 128), 256, gemmSmem>>>(
            nr, wtf + (size_t)i * DD * D4, c_fc_b + (size_t)i * D4,
            fc, D4, DD);

        // m = fc @ Wmlp + b
        gemm3<0><<<dim3(DD / 128, TOKENS / 128), 256, gemmSmem>>>(
            fc, wtm + (size_t)i * D4 * DD, mlp_b + (size_t)i * DD,
            tmp, DD, D4);

        // h = LN(n + m); last layer -> d_out, no rounded copy
        float* dst = (i == NLAYER - 1) ? (float*)d_out : h;
        float* dstr = (i == NLAYER - 1) ? nullptr : hr;
        add_ln_kernel<<<TOKENS, 256>>>(n, tmp, ln2_w + i * DD, ln2_b + i * DD, dst, dstr);
    }
}

// round 8
// speedup vs baseline: 1.8668x; 1.0466x over previous
#include <cuda_runtime.h>
#include <cuda_bf16.h>
#include <cstdint>

// ---------------------------------------------------------------------------
// GPT-1 forward: B=4, S=1024, D=768, H=12, HD=64, N_LAYER=5
// Round 8: flash with cp.async double-buffered K/V (rounding moved to QKV
// epilogue); gemm3 single-barrier k-loop with exact waits.
// ---------------------------------------------------------------------------

#define NB 4
#define SS 1024
#define DD 768
#define HH 12
#define HDD 64
#define NLAYER 5
#define TOKENS (NB * SS)           // 4096
#define D3 (3 * DD)                // 2304
#define D4 (4 * DD)                // 3072

// -------------------- device scratch (no cudaMalloc allowed) ---------------
__device__ __align__(128) float g_h[TOKENS * DD];
__device__ __align__(128) float g_hr[TOKENS * DD];
__device__ __align__(128) float g_n[TOKENS * DD];
__device__ __align__(128) float g_nr[TOKENS * DD];
__device__ __align__(128) float g_tmp[TOKENS * DD];
__device__ __align__(128) float g_attn[TOKENS * DD];
__device__ __align__(128) float g_qkv[TOKENS * D3];
__device__ __align__(128) float g_fc[TOKENS * D4];
__device__ __align__(128) float g_wta[NLAYER * DD * D3];
__device__ __align__(128) float g_wtp[NLAYER * DD * DD];
__device__ __align__(128) float g_wtf[NLAYER * DD * D4];
__device__ __align__(128) float g_wtm[NLAYER * D4 * DD];
__device__ int g_is_i64;

// -------------------- helpers ----------------------------------------------
__device__ __forceinline__ float warp_sum(float v) {
    #pragma unroll
    for (int o = 16; o; o >>= 1) v += __shfl_xor_sync(0xffffffffu, v, o);
    return v;
}
__device__ __forceinline__ float gelu_f(float x) {
    const float c2 = 1.5957691216057308f;  // 2*sqrt(2/pi)
    float u = c2 * (x + 0.044715f * x * x * x);
    return x / (1.0f + __expf(-u));
}
__device__ __forceinline__ uint32_t to_tf32(float x) {
    uint32_t u;
    asm("cvt.rna.tf32.f32 %0, %1;" : "=r"(u) : "f"(x));
    return u;
}
__device__ __forceinline__ float to_tf32f(float x) {
    return __uint_as_float(to_tf32(x));
}
__device__ __forceinline__ void mma8(float* c, const uint32_t* a, const uint32_t* b) {
    asm volatile(
        "mma.sync.aligned.m16n8k8.row.col.f32.tf32.tf32.f32 "
        "{%0,%1,%2,%3},{%4,%5,%6,%7},{%8,%9},{%0,%1,%2,%3};\n"
        : "+f"(c[0]), "+f"(c[1]), "+f"(c[2]), "+f"(c[3])
        : "r"(a[0]), "r"(a[1]), "r"(a[2]), "r"(a[3]), "r"(b[0]), "r"(b[1]));
}
__device__ __forceinline__ void ldsm4(uint32_t* r, uint32_t addr) {
    asm volatile("ldmatrix.sync.aligned.m8n8.x4.shared.b16 {%0,%1,%2,%3}, [%4];"
                 : "=r"(r[0]), "=r"(r[1]), "=r"(r[2]), "=r"(r[3]) : "r"(addr));
}
__device__ __forceinline__ void cpasync16(uint32_t dst, const float* src) {
    asm volatile("cp.async.cg.shared.global [%0], [%1], 16;" :: "r"(dst), "l"(src));
}

// -------------------- input_ids dtype detection ----------------------------
__global__ void detect_kernel(const int* __restrict__ ids) {
    int any = 0;
    for (int i = 1; i < 64; i += 2) any |= ids[i];
    g_is_i64 = (any == 0) ? 1 : 0;
}

// -------------------- embedding (dual write: fp32 + tf32-rounded) ----------
__global__ void embed_kernel(const int* __restrict__ ids,
                             const float* __restrict__ tok,
                             const float* __restrict__ pos,
                             float* __restrict__ h,
                             float* __restrict__ hr) {
    int i = blockIdx.x * blockDim.x + threadIdx.x;
    if (i >= TOKENS * DD) return;
    int t = i / DD;
    int d = i - t * DD;
    int s = t & (SS - 1);
    int id = g_is_i64 ? ids[2 * t] : ids[t];
    float v = tok[(size_t)id * DD + d] + pos[(size_t)s * DD + d];
    h[i] = v;
    hr[i] = to_tf32f(v);
}

// -------------------- weight transpose + rna round: [K][N] -> [N][K] -------
__global__ void transpose_w(const float* __restrict__ src,
                            float* __restrict__ dst, int K, int N) {
    __shared__ float t[32][33];
    int n0 = blockIdx.x * 32, k0 = blockIdx.y * 32;
    size_t off = (size_t)blockIdx.z * K * N;
    int tx = threadIdx.x, ty = threadIdx.y;
    #pragma unroll
    for (int i = 0; i < 4; i++)
        t[ty + i * 8][tx] = src[off + (size_t)(k0 + ty + i * 8) * N + n0 + tx];
    __syncthreads();
    #pragma unroll
    for (int i = 0; i < 4; i++)
        dst[off + (size_t)(n0 + ty + i * 8) * K + k0 + tx] =
            to_tf32f(t[tx][ty + i * 8]);
}

// ---------------------------------------------------------------------------
// cp.async 3-stage tf32 GEMM.  A [M][K] pre-rounded, Bt [N][K] pre-rounded.
// 128x128x16 tiles, 8 warps of 64x32, ldmatrix frags from [r][20] smem.
// One barrier per k-tile; exact tail waits.
// MODE 0: +bias.  MODE 1: rna(gelu(+bias)).  MODE 2: rna(+bias).
// ---------------------------------------------------------------------------
template<int MODE>
__global__ __launch_bounds__(256, 2)
void gemm3(const float* __restrict__ A,
           const float* __restrict__ Bt,
           const float* __restrict__ bias,
           float* __restrict__ C, int ldc,
           int K) {
    constexpr int BM = 128, BN = 128, BK = 16;
    constexpr int SW = BM * 20;              // words per operand stage

    extern __shared__ float dyn[];
    float* AsBase = dyn;                      // 3 stages A
    float* BsBase = dyn + 3 * SW;             // 3 stages B

    const int tid  = threadIdx.x;
    const int wid  = tid >> 5;
    const int lane = tid & 31;
    const int g    = lane >> 2;
    const int tg   = lane & 3;
    const int warpM = (wid >> 2) * 64;
    const int warpN = (wid & 3) * 32;
    const int rowBase = blockIdx.y * BM;
    const int colBase = blockIdx.x * BN;

    const uint32_t aSm = (uint32_t)__cvta_generic_to_shared(AsBase);
    const uint32_t bSm = (uint32_t)__cvta_generic_to_shared(BsBase);
    const uint32_t aLaneOff = ((lane & 15) * 20 + ((lane & 16) ? 4 : 0)) * 4;
    const uint32_t bLaneOff = ((((lane & 7) | ((lane & 16) >> 1))) * 20 +
                               ((lane & 8) ? 4 : 0)) * 4;

    const int r  = tid >> 2;        // 0..63 (+64 for second batch)
    const int kq = tid & 3;

    float acc[4][4][4];
    #pragma unroll
    for (int i = 0; i < 4; i++)
        #pragma unroll
        for (int j = 0; j < 4; j++)
            #pragma unroll
            for (int q = 0; q < 4; q++) acc[i][j][q] = 0.0f;

    auto stage = [&](int kt, int buf) {
        int k0 = kt * BK;
        uint32_t aB = aSm + buf * SW * 4;
        uint32_t bB = bSm + buf * SW * 4;
        #pragma unroll
        for (int it = 0; it < 2; it++) {
            int rr = r + it * 64;
            cpasync16(aB + (rr * 20 + kq * 4) * 4,
                      A + (size_t)(rowBase + rr) * K + k0 + kq * 4);
        }
        #pragma unroll
        for (int it = 0; it < 2; it++) {
            int nn = r + it * 64;
            cpasync16(bB + (nn * 20 + kq * 4) * 4,
                      Bt + (size_t)(colBase + nn) * K + k0 + kq * 4);
        }
        asm volatile("cp.async.commit_group;");
    };

    const int KT = K / BK;
    stage(0, 0);
    stage(1, 1);

    for (int kt = 0; kt < KT; kt++) {
        if (kt == KT - 1)
            asm volatile("cp.async.wait_group 0;");
        else
            asm volatile("cp.async.wait_group 1;");
        __syncthreads();
        if (kt + 2 < KT) stage(kt + 2, (kt + 2) % 3);

        int buf = kt % 3;
        uint32_t aBase = aSm + buf * SW * 4 + aLaneOff + (warpM * 20) * 4;
        uint32_t bBase = bSm + buf * SW * 4 + bLaneOff + (warpN * 20) * 4;
        #pragma unroll
        for (int kk = 0; kk < BK; kk += 8) {
            uint32_t af[4][4];
            #pragma unroll
            for (int i = 0; i < 4; i++)
                ldsm4(af[i], aBase + kk * 4 + i * (16 * 20 * 4));
            uint32_t bf[4][2];
            {
                uint32_t t[4];
                ldsm4(t, bBase + kk * 4);
                bf[0][0] = t[0]; bf[0][1] = t[1];
                bf[1][0] = t[2]; bf[1][1] = t[3];
                ldsm4(t, bBase + kk * 4 + 16 * 20 * 4);
                bf[2][0] = t[0]; bf[2][1] = t[1];
                bf[3][0] = t[2]; bf[3][1] = t[3];
            }
            #pragma unroll
            for (int i = 0; i < 4; i++)
                #pragma unroll
                for (int j = 0; j < 4; j++)
                    mma8(acc[i][j], af[i], bf[j]);
        }
    }

    #pragma unroll
    for (int i = 0; i < 4; i++) {
        int r0 = rowBase + warpM + i * 16 + g;
        int r1 = r0 + 8;
        #pragma unroll
        for (int j = 0; j < 4; j++) {
            int c = colBase + warpN + j * 8 + tg * 2;
            float bb0 = bias[c], bb1 = bias[c + 1];
            float v0 = acc[i][j][0] + bb0, v1 = acc[i][j][1] + bb1;
            float v2 = acc[i][j][2] + bb0, v3 = acc[i][j][3] + bb1;
            if (MODE == 1) {
                v0 = to_tf32f(gelu_f(v0)); v1 = to_tf32f(gelu_f(v1));
                v2 = to_tf32f(gelu_f(v2)); v3 = to_tf32f(gelu_f(v3));
            }
            if (MODE == 2) {
                v0 = to_tf32f(v0); v1 = to_tf32f(v1);
                v2 = to_tf32f(v2); v3 = to_tf32f(v3);
            }
            *reinterpret_cast<float2*>(C + (size_t)r0 * ldc + c) = make_float2(v0, v1);
            *reinterpret_cast<float2*>(C + (size_t)r1 * ldc + c) = make_float2(v2, v3);
        }
    }
}

// ---------------------------------------------------------------------------
// Fused flash attention: 128 q-rows/CTA, 8 warps (16 rows each).
// Inputs (qkv) are pre-rounded to tf32 by the QKV GEMM epilogue.
// K/V double-buffered via cp.async; mask row loaded once per CTA.
// ---------------------------------------------------------------------------
#define FS 68

__global__ __launch_bounds__(256)
void flash_kernel(const float* __restrict__ qkv,
                  const float* __restrict__ mask,
                  float* __restrict__ attn) {
    extern __shared__ float sm[];
    float* Qs  = sm;                      // [128 m][68 d]
    float* Ks  = Qs + 128 * FS;           // [2][64 t][68 d]
    float* Vs  = Ks + 2 * 64 * FS;        // [2][64 t][68 d]
    float* Ems = Vs + 2 * 64 * FS;        // [1024]

    const int tid  = threadIdx.x;
    const int wid  = tid >> 5;
    const int lane = tid & 31;
    const int g    = lane >> 2;
    const int tg   = lane & 3;
    const int qBase = blockIdx.x * 128;
    const int bh = blockIdx.y;
    const int b = bh / HH, h = bh - b * HH;

    const float* Qg = qkv + (size_t)b * SS * D3 + h * HDD;
    const float* Kg = Qg + DD;
    const float* Vg = Qg + 2 * DD;

    const uint32_t qSm = (uint32_t)__cvta_generic_to_shared(Qs);
    const uint32_t kSm = (uint32_t)__cvta_generic_to_shared(Ks);
    const uint32_t vSm = (uint32_t)__cvta_generic_to_shared(Vs);

    // ---- stage Q (cp.async) ----
    #pragma unroll
    for (int i = 0; i < 8; i++) {
        int idx = i * 256 + tid;
        int r = idx >> 4, dq = idx & 15;
        cpasync16(qSm + (r * FS + dq * 4) * 4,
                  Qg + (size_t)(qBase + r) * D3 + dq * 4);
    }
    // ---- stage K/V block 0 (same group as Q) ----
    auto stageKV = [&](int kb, int buf) {
        uint32_t kD = kSm + buf * 64 * FS * 4;
        uint32_t vD = vSm + buf * 64 * FS * 4;
        const float* Kt = Kg + (size_t)(kb * 64) * D3;
        const float* Vt = Vg + (size_t)(kb * 64) * D3;
        #pragma unroll
        for (int i = 0; i < 4; i++) {
            int idx = i * 256 + tid;
            int kt = idx >> 4, dq = idx & 15;
            cpasync16(kD + (kt * FS + dq * 4) * 4, Kt + (size_t)kt * D3 + dq * 4);
            cpasync16(vD + (kt * FS + dq * 4) * 4, Vt + (size_t)kt * D3 + dq * 4);
        }
        asm volatile("cp.async.commit_group;");
    };
    stageKV(0, 0);

    // ---- full extended-mask row (plain loads; ordered by first barrier) ----
    #pragma unroll
    for (int i = 0; i < 4; i++) {
        int idx = i * 256 + tid;
        Ems[idx] = (1.0f - mask[b * SS + idx]) * (-3.402823466e38f);
    }

    float o[8][4];
    #pragma unroll
    for (int j = 0; j < 8; j++)
        #pragma unroll
        for (int q = 0; q < 4; q++) o[j][q] = 0.0f;
    float mrow0 = -1e30f, mrow1 = -1e30f;
    float lrow0 = 0.f, lrow1 = 0.f;

    const int row0 = qBase + wid * 16 + g;
    const int row1 = row0 + 8;
    const int srcA = (lane & 28) | (tg >> 1);
    const int srcB = srcA | 2;
    const int e1   = tg & 1;

    const uint32_t aOff = ((wid * 16 + (lane & 15)) * FS + ((lane & 16) ? 4 : 0)) * 4;
    const uint32_t bOff = ((((lane & 7) | ((lane & 16) >> 1))) * FS +
                           ((lane & 8) ? 4 : 0)) * 4;

    const int nkb = blockIdx.x * 2 + 2;
    for (int kb = 0; kb < nkb; kb++) {
        asm volatile("cp.async.wait_group 0;");
        __syncthreads();
        if (kb + 1 < nkb) stageKV(kb + 1, (kb + 1) & 1);

        const uint32_t kBuf = kSm + (kb & 1) * 64 * FS * 4;
        const float*  VsB  = Vs + (kb & 1) * 64 * FS;

        // ---- S = Q @ K^T (16x64 per warp) ----
        float s[8][4];
        #pragma unroll
        for (int j = 0; j < 8; j++)
            #pragma unroll
            for (int q = 0; q < 4; q++) s[j][q] = 0.0f;

        #pragma unroll
        for (int kk = 0; kk < 8; kk++) {
            uint32_t af[4];
            ldsm4(af, qSm + aOff + kk * 8 * 4);
            uint32_t bf[8][2];
            #pragma unroll
            for (int m = 0; m < 4; m++) {
                uint32_t t4[4];
                ldsm4(t4, kBuf + bOff + (m * 16 * FS + kk * 8) * 4);
                bf[2 * m][0] = t4[0]; bf[2 * m][1] = t4[1];
                bf[2 * m + 1][0] = t4[2]; bf[2 * m + 1][1] = t4[3];
            }
            #pragma unroll
            for (int j = 0; j < 8; j++)
                mma8(s[j], af, bf[j]);
        }

        // ---- scale + causal + ext mask, online softmax ----
        float mx0 = -1e30f, mx1 = -1e30f;
        #pragma unroll
        for (int j = 0; j < 8; j++) {
            int c0 = kb * 64 + j * 8 + tg * 2;
            float em0 = Ems[c0];
            float em1 = Ems[c0 + 1];
            float v0 = s[j][0] * 0.125f;
            float v1 = s[j][1] * 0.125f;
            float v2 = s[j][2] * 0.125f;
            float v3 = s[j][3] * 0.125f;
            if (c0 > row0)     v0 = -1e4f;
            if (c0 + 1 > row0) v1 = -1e4f;
            if (c0 > row1)     v2 = -1e4f;
            if (c0 + 1 > row1) v3 = -1e4f;
            v0 += em0; v1 += em1; v2 += em0; v3 += em1;
            s[j][0] = v0; s[j][1] = v1; s[j][2] = v2; s[j][3] = v3;
            mx0 = fmaxf(mx0, fmaxf(v0, v1));
            mx1 = fmaxf(mx1, fmaxf(v2, v3));
        }
        mx0 = fmaxf(mx0, __shfl_xor_sync(0xffffffffu, mx0, 1));
        mx0 = fmaxf(mx0, __shfl_xor_sync(0xffffffffu, mx0, 2));
        mx1 = fmaxf(mx1, __shfl_xor_sync(0xffffffffu, mx1, 1));
        mx1 = fmaxf(mx1, __shfl_xor_sync(0xffffffffu, mx1, 2));

        float mn0 = fmaxf(mrow0, mx0);
        float mn1 = fmaxf(mrow1, mx1);
        float al0 = __expf(mrow0 - mn0);
        float al1 = __expf(mrow1 - mn1);
        mrow0 = mn0; mrow1 = mn1;

        float sum0 = 0.f, sum1 = 0.f;
        #pragma unroll
        for (int j = 0; j < 8; j++) {
            float p0 = __expf(s[j][0] - mn0);
            float p1 = __expf(s[j][1] - mn0);
            float p2 = __expf(s[j][2] - mn1);
            float p3 = __expf(s[j][3] - mn1);
            s[j][0] = p0; s[j][1] = p1; s[j][2] = p2; s[j][3] = p3;
            sum0 += p0 + p1; sum1 += p2 + p3;
        }
        sum0 += __shfl_xor_sync(0xffffffffu, sum0, 1);
        sum0 += __shfl_xor_sync(0xffffffffu, sum0, 2);
        sum1 += __shfl_xor_sync(0xffffffffu, sum1, 1);
        sum1 += __shfl_xor_sync(0xffffffffu, sum1, 2);
        lrow0 = lrow0 * al0 + sum0;
        lrow1 = lrow1 * al1 + sum1;

        #pragma unroll
        for (int jo = 0; jo < 8; jo++) {
            o[jo][0] *= al0; o[jo][1] *= al0;
            o[jo][2] *= al1; o[jo][3] *= al1;
        }

        // ---- O += P @ V : C-frag -> A-frag via intra-quad shuffles ----
        #pragma unroll
        for (int j = 0; j < 8; j++) {
            float x0A = __shfl_sync(0xffffffffu, s[j][0], srcA);
            float x1A = __shfl_sync(0xffffffffu, s[j][1], srcA);
            float x0B = __shfl_sync(0xffffffffu, s[j][0], srcB);
            float x1B = __shfl_sync(0xffffffffu, s[j][1], srcB);
            float y0A = __shfl_sync(0xffffffffu, s[j][2], srcA);
            float y1A = __shfl_sync(0xffffffffu, s[j][3], srcA);
            float y0B = __shfl_sync(0xffffffffu, s[j][2], srcB);
            float y1B = __shfl_sync(0xffffffffu, s[j][3], srcB);
            uint32_t pa[4];
            pa[0] = to_tf32(e1 ? x1A : x0A);
            pa[1] = to_tf32(e1 ? y1A : y0A);
            pa[2] = to_tf32(e1 ? x1B : x0B);
            pa[3] = to_tf32(e1 ? y1B : y0B);
            #pragma unroll
            for (int jo = 0; jo < 8; jo++) {
                uint32_t bf[2];
                bf[0] = __float_as_uint(VsB[(j * 8 + tg) * FS + jo * 8 + g]);
                bf[1] = __float_as_uint(VsB[(j * 8 + tg + 4) * FS + jo * 8 + g]);
                mma8(o[jo], pa, bf);
            }
        }
    }

    // ---- normalize, round, write out ----
    float inv0 = 1.0f / lrow0;
    float inv1 = 1.0f / lrow1;
    #pragma unroll
    for (int jo = 0; jo < 8; jo++) {
        int col = h * HDD + jo * 8 + tg * 2;
        *reinterpret_cast<float2*>(attn + (size_t)(b * SS + row0) * DD + col) =
            make_float2(to_tf32f(o[jo][0] * inv0), to_tf32f(o[jo][1] * inv0));
        *reinterpret_cast<float2*>(attn + (size_t)(b * SS + row1) * DD + col) =
            make_float2(to_tf32f(o[jo][2] * inv1), to_tf32f(o[jo][3] * inv1));
    }
}

// -------------------- fused residual-add + LayerNorm (dual write) ----------
__global__ void add_ln_kernel(const float* __restrict__ x,
                              const float* __restrict__ y,
                              const float* __restrict__ w,
                              const float* __restrict__ b,
                              float* __restrict__ out,
                              float* __restrict__ out_r) {
    int row = blockIdx.x;
    const float* xr = x + (size_t)row * DD;
    const float* yr = y + (size_t)row * DD;
    int tid = threadIdx.x;

    float v0 = xr[tid] + yr[tid];
    float v1 = xr[tid + 256] + yr[tid + 256];
    float v2 = xr[tid + 512] + yr[tid + 512];

    __shared__ float sh[8];
    float s = warp_sum(v0 + v1 + v2);
    if ((tid & 31) == 0) sh[tid >> 5] = s;
    __syncthreads();
    float tot = 0.f;
    #pragma unroll
    for (int i = 0; i < 8; i++) tot += sh[i];
    float mu = tot * (1.0f / DD);
    __syncthreads();

    float d0 = v0 - mu, d1 = v1 - mu, d2 = v2 - mu;
    float s2 = warp_sum(d0 * d0 + d1 * d1 + d2 * d2);
    if ((tid & 31) == 0) sh[tid >> 5] = s2;
    __syncthreads();
    float tot2 = 0.f;
    #pragma unroll
    for (int i = 0; i < 8; i++) tot2 += sh[i];
    float r = rsqrtf(tot2 * (1.0f / DD) + 1e-5f);

    float o0 = d0 * r * w[tid]       + b[tid];
    float o1 = d1 * r * w[tid + 256] + b[tid + 256];
    float o2 = d2 * r * w[tid + 512] + b[tid + 512];
    float* orow = out + (size_t)row * DD;
    orow[tid] = o0; orow[tid + 256] = o1; orow[tid + 512] = o2;
    if (out_r) {
        float* rrow = out_r + (size_t)row * DD;
        rrow[tid]       = to_tf32f(o0);
        rrow[tid + 256] = to_tf32f(o1);
        rrow[tid + 512] = to_tf32f(o2);
    }
}

// ---------------------------------------------------------------------------
extern "C" void kernel_launch(void* const* d_in, const int* in_sizes, int n_in,
                              void* d_out, int out_size) {
    const int*   ids      = (const int*)  d_in[0];
    const float* mask     = (const float*)d_in[2];
    const float* tok_emb  = (const float*)d_in[3];
    const float* pos_emb  = (const float*)d_in[4];
    const float* c_attn_w = (const float*)d_in[5];
    const float* c_attn_b = (const float*)d_in[6];
    const float* c_proj_w = (const float*)d_in[7];
    const float* c_proj_b = (const float*)d_in[8];
    const float* ln1_w    = (const float*)d_in[9];
    const float* ln1_b    = (const float*)d_in[10];
    const float* c_fc_w   = (const float*)d_in[11];
    const float* c_fc_b   = (const float*)d_in[12];
    const float* mlp_w    = (const float*)d_in[13];
    const float* mlp_b    = (const float*)d_in[14];
    const float* ln2_w    = (const float*)d_in[15];
    const float* ln2_b    = (const float*)d_in[16];

    float *h, *hr, *n, *nr, *tmp, *attn, *qkv, *fc;
    float *wta, *wtp, *wtf, *wtm;
    cudaGetSymbolAddress((void**)&h,    g_h);
    cudaGetSymbolAddress((void**)&hr,   g_hr);
    cudaGetSymbolAddress((void**)&n,    g_n);
    cudaGetSymbolAddress((void**)&nr,   g_nr);
    cudaGetSymbolAddress((void**)&tmp,  g_tmp);
    cudaGetSymbolAddress((void**)&attn, g_attn);
    cudaGetSymbolAddress((void**)&qkv,  g_qkv);
    cudaGetSymbolAddress((void**)&fc,   g_fc);
    cudaGetSymbolAddress((void**)&wta,  g_wta);
    cudaGetSymbolAddress((void**)&wtp,  g_wtp);
    cudaGetSymbolAddress((void**)&wtf,  g_wtf);
    cudaGetSymbolAddress((void**)&wtm,  g_wtm);

    const int gemmSmem  = 3 * 2 * 128 * 20 * 4;                        // 61440 B
    const int flashSmem = (128 * FS + 4 * 64 * FS + 1024) * 4;         // 108544 B
    static int s_attr_set = 0;
    if (!s_attr_set) {
        cudaFuncSetAttribute(gemm3<0>, cudaFuncAttributeMaxDynamicSharedMemorySize, gemmSmem);
        cudaFuncSetAttribute(gemm3<1>, cudaFuncAttributeMaxDynamicSharedMemorySize, gemmSmem);
        cudaFuncSetAttribute(gemm3<2>, cudaFuncAttributeMaxDynamicSharedMemorySize, gemmSmem);
        cudaFuncSetAttribute(flash_kernel, cudaFuncAttributeMaxDynamicSharedMemorySize, flashSmem);
        s_attr_set = 1;
    }

    detect_kernel<<<1, 1>>>(ids);
    embed_kernel<<<(TOKENS * DD + 255) / 256, 256>>>(ids, tok_emb, pos_emb, h, hr);

    // one-time weight transposes (tf32-rounded)
    dim3 tb(32, 8);
    transpose_w<<<dim3(D3 / 32, DD / 32, NLAYER), tb>>>(c_attn_w, wta, DD, D3);
    transpose_w<<<dim3(DD / 32, DD / 32, NLAYER), tb>>>(c_proj_w, wtp, DD, DD);
    transpose_w<<<dim3(D4 / 32, DD / 32, NLAYER), tb>>>(c_fc_w,   wtf, DD, D4);
    transpose_w<<<dim3(DD / 32, D4 / 32, NLAYER), tb>>>(mlp_w,    wtm, D4, DD);

    for (int i = 0; i < NLAYER; i++) {
        // QKV: hr [4096,768] @ Wt [2304,768]^T  (output tf32-rounded for flash)
        gemm3<2><<<dim3(D3 / 128, TOKENS / 128), 256, gemmSmem>>>(
            hr, wta + (size_t)i * DD * D3, c_attn_b + (size_t)i * D3,
            qkv, D3, DD);

        // fused flash attention -> attn (tf32-rounded)
        flash_kernel<<<dim3(SS / 128, NB * HH), 256, flashSmem>>>(qkv, mask, attn);

        // attn out projection
        gemm3<0><<<dim3(DD / 128, TOKENS / 128), 256, gemmSmem>>>(
            attn, wtp + (size_t)i * DD * DD, c_proj_b + (size_t)i * DD,
            tmp, DD, DD);

        // n = LN(h + attn_proj), nr = rna(n)
        add_ln_kernel<<<TOKENS, 256>>>(h, tmp, ln1_w + i * DD, ln1_b + i * DD, n, nr);

        // fc = rna(gelu(nr @ Wfc + b))
        gemm3<1><<<dim3(D4 / 128, TOKENS / 128), 256, gemmSmem>>>(
            nr, wtf + (size_t)i * DD * D4, c_fc_b + (size_t)i * D4,
            fc, D4, DD);

        // m = fc @ Wmlp + b
        gemm3<0><<<dim3(DD / 128, TOKENS / 128), 256, gemmSmem>>>(
            fc, wtm + (size_t)i * D4 * DD, mlp_b + (size_t)i * DD,
            tmp, DD, D4);

        // h = LN(n + m); last layer -> d_out, no rounded copy
        float* dst = (i == NLAYER - 1) ? (float*)d_out : h;
        float* dstr = (i == NLAYER - 1) ? nullptr : hr;
        add_ln_kernel<<<TOKENS, 256>>>(n, tmp, ln2_w + i * DD, ln2_b + i * DD, dst, dstr);
    }
}

// round 9
// speedup vs baseline: 2.0176x; 1.0807x over previous
#include <cuda_runtime.h>
#include <cuda_bf16.h>
#include <cstdint>

// ---------------------------------------------------------------------------
// GPT-1 forward: B=4, S=1024, D=768, H=12, HD=64, N_LAYER=5
// Round 9: gemm3 with BK=32 (3-stage cp.async, 2 CTAs/SM); flash q-tile
// reversal; merged transpose launch.
// ---------------------------------------------------------------------------

#define NB 4
#define SS 1024
#define DD 768
#define HH 12
#define HDD 64
#define NLAYER 5
#define TOKENS (NB * SS)           // 4096
#define D3 (3 * DD)                // 2304
#define D4 (4 * DD)                // 3072

// -------------------- device scratch (no cudaMalloc allowed) ---------------
__device__ __align__(128) float g_h[TOKENS * DD];
__device__ __align__(128) float g_hr[TOKENS * DD];
__device__ __align__(128) float g_n[TOKENS * DD];
__device__ __align__(128) float g_nr[TOKENS * DD];
__device__ __align__(128) float g_tmp[TOKENS * DD];
__device__ __align__(128) float g_attn[TOKENS * DD];
__device__ __align__(128) float g_qkv[TOKENS * D3];
__device__ __align__(128) float g_fc[TOKENS * D4];
__device__ __align__(128) float g_wta[NLAYER * DD * D3];
__device__ __align__(128) float g_wtp[NLAYER * DD * DD];
__device__ __align__(128) float g_wtf[NLAYER * DD * D4];
__device__ __align__(128) float g_wtm[NLAYER * D4 * DD];
__device__ int g_is_i64;

// -------------------- helpers ----------------------------------------------
__device__ __forceinline__ float warp_sum(float v) {
    #pragma unroll
    for (int o = 16; o; o >>= 1) v += __shfl_xor_sync(0xffffffffu, v, o);
    return v;
}
__device__ __forceinline__ float gelu_f(float x) {
    const float c2 = 1.5957691216057308f;  // 2*sqrt(2/pi)
    float u = c2 * (x + 0.044715f * x * x * x);
    return x / (1.0f + __expf(-u));
}
__device__ __forceinline__ uint32_t to_tf32(float x) {
    uint32_t u;
    asm("cvt.rna.tf32.f32 %0, %1;" : "=r"(u) : "f"(x));
    return u;
}
__device__ __forceinline__ float to_tf32f(float x) {
    return __uint_as_float(to_tf32(x));
}
__device__ __forceinline__ void mma8(float* c, const uint32_t* a, const uint32_t* b) {
    asm volatile(
        "mma.sync.aligned.m16n8k8.row.col.f32.tf32.tf32.f32 "
        "{%0,%1,%2,%3},{%4,%5,%6,%7},{%8,%9},{%0,%1,%2,%3};\n"
        : "+f"(c[0]), "+f"(c[1]), "+f"(c[2]), "+f"(c[3])
        : "r"(a[0]), "r"(a[1]), "r"(a[2]), "r"(a[3]), "r"(b[0]), "r"(b[1]));
}
__device__ __forceinline__ void ldsm4(uint32_t* r, uint32_t addr) {
    asm volatile("ldmatrix.sync.aligned.m8n8.x4.shared.b16 {%0,%1,%2,%3}, [%4];"
                 : "=r"(r[0]), "=r"(r[1]), "=r"(r[2]), "=r"(r[3]) : "r"(addr));
}
__device__ __forceinline__ void cpasync16(uint32_t dst, const float* src) {
    asm volatile("cp.async.cg.shared.global [%0], [%1], 16;" :: "r"(dst), "l"(src));
}

// -------------------- input_ids dtype detection ----------------------------
__global__ void detect_kernel(const int* __restrict__ ids) {
    int any = 0;
    for (int i = 1; i < 64; i += 2) any |= ids[i];
    g_is_i64 = (any == 0) ? 1 : 0;
}

// -------------------- embedding (dual write: fp32 + tf32-rounded) ----------
__global__ void embed_kernel(const int* __restrict__ ids,
                             const float* __restrict__ tok,
                             const float* __restrict__ pos,
                             float* __restrict__ h,
                             float* __restrict__ hr) {
    int i = blockIdx.x * blockDim.x + threadIdx.x;
    if (i >= TOKENS * DD) return;
    int t = i / DD;
    int d = i - t * DD;
    int s = t & (SS - 1);
    int id = g_is_i64 ? ids[2 * t] : ids[t];
    float v = tok[(size_t)id * DD + d] + pos[(size_t)s * DD + d];
    h[i] = v;
    hr[i] = to_tf32f(v);
}

// -------------------- all weight transposes in ONE launch -------------------
// [K][N] -> [N][K] with rna rounding.  1-D grid, segment decode.
#define TA_TILES (NLAYER * (D3 / 32) * (DD / 32))   // 8640
#define TP_TILES (NLAYER * (DD / 32) * (DD / 32))   // 2880
#define TF_TILES (NLAYER * (D4 / 32) * (DD / 32))   // 11520
#define TM_TILES (NLAYER * (DD / 32) * (D4 / 32))   // 11520
#define T_TOTAL  (TA_TILES + TP_TILES + TF_TILES + TM_TILES)

__global__ void transpose_all(const float* __restrict__ wa, float* __restrict__ ta,
                              const float* __restrict__ wp, float* __restrict__ tp,
                              const float* __restrict__ wf, float* __restrict__ tf,
                              const float* __restrict__ wm, float* __restrict__ tm) {
    __shared__ float t[32][33];
    int bid = blockIdx.x;
    const float* src; float* dst; int K, N;
    if (bid < TA_TILES)            { src = wa; dst = ta; K = DD; N = D3; }
    else if (bid < TA_TILES + TP_TILES) {
        bid -= TA_TILES;            src = wp; dst = tp; K = DD; N = DD; }
    else if (bid < TA_TILES + TP_TILES + TF_TILES) {
        bid -= TA_TILES + TP_TILES; src = wf; dst = tf; K = DD; N = D4; }
    else {
        bid -= TA_TILES + TP_TILES + TF_TILES;
                                    src = wm; dst = tm; K = D4; N = DD; }
    int ntx = N / 32;
    int per = ntx * (K / 32);
    int layer = bid / per;
    int tt = bid - layer * per;
    int n0 = (tt % ntx) * 32;
    int k0 = (tt / ntx) * 32;
    size_t off = (size_t)layer * K * N;

    int tx = threadIdx.x, ty = threadIdx.y;
    #pragma unroll
    for (int i = 0; i < 4; i++)
        t[ty + i * 8][tx] = src[off + (size_t)(k0 + ty + i * 8) * N + n0 + tx];
    __syncthreads();
    #pragma unroll
    for (int i = 0; i < 4; i++)
        dst[off + (size_t)(n0 + ty + i * 8) * K + k0 + tx] =
            to_tf32f(t[tx][ty + i * 8]);
}

// ---------------------------------------------------------------------------
// cp.async 3-stage tf32 GEMM, BK=32.  A [M][K], Bt [N][K] (both pre-rounded).
// 128x128x32 tiles, 8 warps of 64x32, ldmatrix frags from [r][36] smem.
// MODE 0: +bias.  MODE 1: rna(gelu(+bias)).  MODE 2: rna(+bias).
// ---------------------------------------------------------------------------
template<int MODE>
__global__ __launch_bounds__(256, 2)
void gemm3(const float* __restrict__ A,
           const float* __restrict__ Bt,
           const float* __restrict__ bias,
           float* __restrict__ C, int ldc,
           int K) {
    constexpr int BM = 128, BK = 32;
    constexpr int RS = BK + 4;               // 36-word row stride
    constexpr int SW = BM * RS;              // words per operand stage

    extern __shared__ float dyn[];
    float* AsBase = dyn;                      // 3 stages A
    float* BsBase = dyn + 3 * SW;             // 3 stages B

    const int tid  = threadIdx.x;
    const int wid  = tid >> 5;
    const int lane = tid & 31;
    const int g    = lane >> 2;
    const int tg   = lane & 3;
    const int warpM = (wid >> 2) * 64;
    const int warpN = (wid & 3) * 32;
    const int rowBase = blockIdx.y * BM;
    const int colBase = blockIdx.x * BM;

    const uint32_t aSm = (uint32_t)__cvta_generic_to_shared(AsBase);
    const uint32_t bSm = (uint32_t)__cvta_generic_to_shared(BsBase);
    const uint32_t aLaneOff = ((lane & 15) * RS + ((lane & 16) ? 4 : 0)) * 4;
    const uint32_t bLaneOff = ((((lane & 7) | ((lane & 16) >> 1))) * RS +
                               ((lane & 8) ? 4 : 0)) * 4;

    const int r  = tid >> 3;        // 0..31 (+32/64/96 for later batches)
    const int kq = tid & 7;

    float acc[4][4][4];
    #pragma unroll
    for (int i = 0; i < 4; i++)
        #pragma unroll
        for (int j = 0; j < 4; j++)
            #pragma unroll
            for (int q = 0; q < 4; q++) acc[i][j][q] = 0.0f;

    auto stage = [&](int kt, int buf) {
        int k0 = kt * BK;
        uint32_t aB = aSm + buf * SW * 4;
        uint32_t bB = bSm + buf * SW * 4;
        #pragma unroll
        for (int it = 0; it < 4; it++) {
            int rr = r + it * 32;
            cpasync16(aB + (rr * RS + kq * 4) * 4,
                      A + (size_t)(rowBase + rr) * K + k0 + kq * 4);
        }
        #pragma unroll
        for (int it = 0; it < 4; it++) {
            int nn = r + it * 32;
            cpasync16(bB + (nn * RS + kq * 4) * 4,
                      Bt + (size_t)(colBase + nn) * K + k0 + kq * 4);
        }
        asm volatile("cp.async.commit_group;");
    };

    const int KT = K / BK;
    stage(0, 0);
    stage(1, 1);

    for (int kt = 0; kt < KT; kt++) {
        if (kt == KT - 1)
            asm volatile("cp.async.wait_group 0;");
        else
            asm volatile("cp.async.wait_group 1;");
        __syncthreads();
        if (kt + 2 < KT) stage(kt + 2, (kt + 2) % 3);

        int buf = kt % 3;
        uint32_t aBase = aSm + buf * SW * 4 + aLaneOff + (warpM * RS) * 4;
        uint32_t bBase = bSm + buf * SW * 4 + bLaneOff + (warpN * RS) * 4;
        #pragma unroll
        for (int kk = 0; kk < BK; kk += 8) {
            uint32_t af[4][4];
            #pragma unroll
            for (int i = 0; i < 4; i++)
                ldsm4(af[i], aBase + kk * 4 + i * (16 * RS * 4));
            uint32_t bf[4][2];
            {
                uint32_t t[4];
                ldsm4(t, bBase + kk * 4);
                bf[0][0] = t[0]; bf[0][1] = t[1];
                bf[1][0] = t[2]; bf[1][1] = t[3];
                ldsm4(t, bBase + kk * 4 + 16 * RS * 4);
                bf[2][0] = t[0]; bf[2][1] = t[1];
                bf[3][0] = t[2]; bf[3][1] = t[3];
            }
            #pragma unroll
            for (int i = 0; i < 4; i++)
                #pragma unroll
                for (int j = 0; j < 4; j++)
                    mma8(acc[i][j], af[i], bf[j]);
        }
    }

    #pragma unroll
    for (int i = 0; i < 4; i++) {
        int r0 = rowBase + warpM + i * 16 + g;
        int r1 = r0 + 8;
        #pragma unroll
        for (int j = 0; j < 4; j++) {
            int c = colBase + warpN + j * 8 + tg * 2;
            float bb0 = bias[c], bb1 = bias[c + 1];
            float v0 = acc[i][j][0] + bb0, v1 = acc[i][j][1] + bb1;
            float v2 = acc[i][j][2] + bb0, v3 = acc[i][j][3] + bb1;
            if (MODE == 1) {
                v0 = to_tf32f(gelu_f(v0)); v1 = to_tf32f(gelu_f(v1));
                v2 = to_tf32f(gelu_f(v2)); v3 = to_tf32f(gelu_f(v3));
            }
            if (MODE == 2) {
                v0 = to_tf32f(v0); v1 = to_tf32f(v1);
                v2 = to_tf32f(v2); v3 = to_tf32f(v3);
            }
            *reinterpret_cast<float2*>(C + (size_t)r0 * ldc + c) = make_float2(v0, v1);
            *reinterpret_cast<float2*>(C + (size_t)r1 * ldc + c) = make_float2(v2, v3);
        }
    }
}

// ---------------------------------------------------------------------------
// Fused flash attention: 128 q-rows/CTA, 8 warps (16 rows each).
// Inputs (qkv) pre-rounded by the QKV GEMM epilogue.  K/V double-buffered
// via cp.async.  q-tiles processed in REVERSE block order (heavy first).
// ---------------------------------------------------------------------------
#define FS 68

__global__ __launch_bounds__(256)
void flash_kernel(const float* __restrict__ qkv,
                  const float* __restrict__ mask,
                  float* __restrict__ attn) {
    extern __shared__ float sm[];
    float* Qs  = sm;                      // [128 m][68 d]
    float* Ks  = Qs + 128 * FS;           // [2][64 t][68 d]
    float* Vs  = Ks + 2 * 64 * FS;        // [2][64 t][68 d]
    float* Ems = Vs + 2 * 64 * FS;        // [1024]

    const int tid  = threadIdx.x;
    const int wid  = tid >> 5;
    const int lane = tid & 31;
    const int g    = lane >> 2;
    const int tg   = lane & 3;
    const int qi = gridDim.x - 1 - blockIdx.x;   // heavy tiles first
    const int qBase = qi * 128;
    const int bh = blockIdx.y;
    const int b = bh / HH, h = bh - b * HH;

    const float* Qg = qkv + (size_t)b * SS * D3 + h * HDD;
    const float* Kg = Qg + DD;
    const float* Vg = Qg + 2 * DD;

    const uint32_t qSm = (uint32_t)__cvta_generic_to_shared(Qs);
    const uint32_t kSm = (uint32_t)__cvta_generic_to_shared(Ks);
    const uint32_t vSm = (uint32_t)__cvta_generic_to_shared(Vs);

    // ---- stage Q (cp.async) ----
    #pragma unroll
    for (int i = 0; i < 8; i++) {
        int idx = i * 256 + tid;
        int r = idx >> 4, dq = idx & 15;
        cpasync16(qSm + (r * FS + dq * 4) * 4,
                  Qg + (size_t)(qBase + r) * D3 + dq * 4);
    }
    auto stageKV = [&](int kb, int buf) {
        uint32_t kD = kSm + buf * 64 * FS * 4;
        uint32_t vD = vSm + buf * 64 * FS * 4;
        const float* Kt = Kg + (size_t)(kb * 64) * D3;
        const float* Vt = Vg + (size_t)(kb * 64) * D3;
        #pragma unroll
        for (int i = 0; i < 4; i++) {
            int idx = i * 256 + tid;
            int kt = idx >> 4, dq = idx & 15;
            cpasync16(kD + (kt * FS + dq * 4) * 4, Kt + (size_t)kt * D3 + dq * 4);
            cpasync16(vD + (kt * FS + dq * 4) * 4, Vt + (size_t)kt * D3 + dq * 4);
        }
        asm volatile("cp.async.commit_group;");
    };
    stageKV(0, 0);

    // ---- full extended-mask row ----
    #pragma unroll
    for (int i = 0; i < 4; i++) {
        int idx = i * 256 + tid;
        Ems[idx] = (1.0f - mask[b * SS + idx]) * (-3.402823466e38f);
    }

    float o[8][4];
    #pragma unroll
    for (int j = 0; j < 8; j++)
        #pragma unroll
        for (int q = 0; q < 4; q++) o[j][q] = 0.0f;
    float mrow0 = -1e30f, mrow1 = -1e30f;
    float lrow0 = 0.f, lrow1 = 0.f;

    const int row0 = qBase + wid * 16 + g;
    const int row1 = row0 + 8;
    const int srcA = (lane & 28) | (tg >> 1);
    const int srcB = srcA | 2;
    const int e1   = tg & 1;

    const uint32_t aOff = ((wid * 16 + (lane & 15)) * FS + ((lane & 16) ? 4 : 0)) * 4;
    const uint32_t bOff = ((((lane & 7) | ((lane & 16) >> 1))) * FS +
                           ((lane & 8) ? 4 : 0)) * 4;

    const int nkb = qi * 2 + 2;
    for (int kb = 0; kb < nkb; kb++) {
        asm volatile("cp.async.wait_group 0;");
        __syncthreads();
        if (kb + 1 < nkb) stageKV(kb + 1, (kb + 1) & 1);

        const uint32_t kBuf = kSm + (kb & 1) * 64 * FS * 4;
        const float*  VsB  = Vs + (kb & 1) * 64 * FS;

        // ---- S = Q @ K^T (16x64 per warp) ----
        float s[8][4];
        #pragma unroll
        for (int j = 0; j < 8; j++)
            #pragma unroll
            for (int q = 0; q < 4; q++) s[j][q] = 0.0f;

        #pragma unroll
        for (int kk = 0; kk < 8; kk++) {
            uint32_t af[4];
            ldsm4(af, qSm + aOff + kk * 8 * 4);
            uint32_t bf[8][2];
            #pragma unroll
            for (int m = 0; m < 4; m++) {
                uint32_t t4[4];
                ldsm4(t4, kBuf + bOff + (m * 16 * FS + kk * 8) * 4);
                bf[2 * m][0] = t4[0]; bf[2 * m][1] = t4[1];
                bf[2 * m + 1][0] = t4[2]; bf[2 * m + 1][1] = t4[3];
            }
            #pragma unroll
            for (int j = 0; j < 8; j++)
                mma8(s[j], af, bf[j]);
        }

        // ---- scale + causal + ext mask, online softmax ----
        float mx0 = -1e30f, mx1 = -1e30f;
        #pragma unroll
        for (int j = 0; j < 8; j++) {
            int c0 = kb * 64 + j * 8 + tg * 2;
            float em0 = Ems[c0];
            float em1 = Ems[c0 + 1];
            float v0 = s[j][0] * 0.125f;
            float v1 = s[j][1] * 0.125f;
            float v2 = s[j][2] * 0.125f;
            float v3 = s[j][3] * 0.125f;
            if (c0 > row0)     v0 = -1e4f;
            if (c0 + 1 > row0) v1 = -1e4f;
            if (c0 > row1)     v2 = -1e4f;
            if (c0 + 1 > row1) v3 = -1e4f;
            v0 += em0; v1 += em1; v2 += em0; v3 += em1;
            s[j][0] = v0; s[j][1] = v1; s[j][2] = v2; s[j][3] = v3;
            mx0 = fmaxf(mx0, fmaxf(v0, v1));
            mx1 = fmaxf(mx1, fmaxf(v2, v3));
        }
        mx0 = fmaxf(mx0, __shfl_xor_sync(0xffffffffu, mx0, 1));
        mx0 = fmaxf(mx0, __shfl_xor_sync(0xffffffffu, mx0, 2));
        mx1 = fmaxf(mx1, __shfl_xor_sync(0xffffffffu, mx1, 1));
        mx1 = fmaxf(mx1, __shfl_xor_sync(0xffffffffu, mx1, 2));

        float mn0 = fmaxf(mrow0, mx0);
        float mn1 = fmaxf(mrow1, mx1);
        float al0 = __expf(mrow0 - mn0);
        float al1 = __expf(mrow1 - mn1);
        mrow0 = mn0; mrow1 = mn1;

        float sum0 = 0.f, sum1 = 0.f;
        #pragma unroll
        for (int j = 0; j < 8; j++) {
            float p0 = __expf(s[j][0] - mn0);
            float p1 = __expf(s[j][1] - mn0);
            float p2 = __expf(s[j][2] - mn1);
            float p3 = __expf(s[j][3] - mn1);
            s[j][0] = p0; s[j][1] = p1; s[j][2] = p2; s[j][3] = p3;
            sum0 += p0 + p1; sum1 += p2 + p3;
        }
        sum0 += __shfl_xor_sync(0xffffffffu, sum0, 1);
        sum0 += __shfl_xor_sync(0xffffffffu, sum0, 2);
        sum1 += __shfl_xor_sync(0xffffffffu, sum1, 1);
        sum1 += __shfl_xor_sync(0xffffffffu, sum1, 2);
        lrow0 = lrow0 * al0 + sum0;
        lrow1 = lrow1 * al1 + sum1;

        #pragma unroll
        for (int jo = 0; jo < 8; jo++) {
            o[jo][0] *= al0; o[jo][1] *= al0;
            o[jo][2] *= al1; o[jo][3] *= al1;
        }

        // ---- O += P @ V : C-frag -> A-frag via intra-quad shuffles ----
        #pragma unroll
        for (int j = 0; j < 8; j++) {
            float x0A = __shfl_sync(0xffffffffu, s[j][0], srcA);
            float x1A = __shfl_sync(0xffffffffu, s[j][1], srcA);
            float x0B = __shfl_sync(0xffffffffu, s[j][0], srcB);
            float x1B = __shfl_sync(0xffffffffu, s[j][1], srcB);
            float y0A = __shfl_sync(0xffffffffu, s[j][2], srcA);
            float y1A = __shfl_sync(0xffffffffu, s[j][3], srcA);
            float y0B = __shfl_sync(0xffffffffu, s[j][2], srcB);
            float y1B = __shfl_sync(0xffffffffu, s[j][3], srcB);
            uint32_t pa[4];
            pa[0] = to_tf32(e1 ? x1A : x0A);
            pa[1] = to_tf32(e1 ? y1A : y0A);
            pa[2] = to_tf32(e1 ? x1B : x0B);
            pa[3] = to_tf32(e1 ? y1B : y0B);
            #pragma unroll
            for (int jo = 0; jo < 8; jo++) {
                uint32_t bf[2];
                bf[0] = __float_as_uint(VsB[(j * 8 + tg) * FS + jo * 8 + g]);
                bf[1] = __float_as_uint(VsB[(j * 8 + tg + 4) * FS + jo * 8 + g]);
                mma8(o[jo], pa, bf);
            }
        }
    }

    // ---- normalize, round, write out ----
    float inv0 = 1.0f / lrow0;
    float inv1 = 1.0f / lrow1;
    #pragma unroll
    for (int jo = 0; jo < 8; jo++) {
        int col = h * HDD + jo * 8 + tg * 2;
        *reinterpret_cast<float2*>(attn + (size_t)(b * SS + row0) * DD + col) =
            make_float2(to_tf32f(o[jo][0] * inv0), to_tf32f(o[jo][1] * inv0));
        *reinterpret_cast<float2*>(attn + (size_t)(b * SS + row1) * DD + col) =
            make_float2(to_tf32f(o[jo][2] * inv1), to_tf32f(o[jo][3] * inv1));
    }
}

// -------------------- fused residual-add + LayerNorm (dual write) ----------
__global__ void add_ln_kernel(const float* __restrict__ x,
                              const float* __restrict__ y,
                              const float* __restrict__ w,
                              const float* __restrict__ b,
                              float* __restrict__ out,
                              float* __restrict__ out_r) {
    int row = blockIdx.x;
    const float* xr = x + (size_t)row * DD;
    const float* yr = y + (size_t)row * DD;
    int tid = threadIdx.x;

    float v0 = xr[tid] + yr[tid];
    float v1 = xr[tid + 256] + yr[tid + 256];
    float v2 = xr[tid + 512] + yr[tid + 512];

    __shared__ float sh[8];
    float s = warp_sum(v0 + v1 + v2);
    if ((tid & 31) == 0) sh[tid >> 5] = s;
    __syncthreads();
    float tot = 0.f;
    #pragma unroll
    for (int i = 0; i < 8; i++) tot += sh[i];
    float mu = tot * (1.0f / DD);
    __syncthreads();

    float d0 = v0 - mu, d1 = v1 - mu, d2 = v2 - mu;
    float s2 = warp_sum(d0 * d0 + d1 * d1 + d2 * d2);
    if ((tid & 31) == 0) sh[tid >> 5] = s2;
    __syncthreads();
    float tot2 = 0.f;
    #pragma unroll
    for (int i = 0; i < 8; i++) tot2 += sh[i];
    float r = rsqrtf(tot2 * (1.0f / DD) + 1e-5f);

    float o0 = d0 * r * w[tid]       + b[tid];
    float o1 = d1 * r * w[tid + 256] + b[tid + 256];
    float o2 = d2 * r * w[tid + 512] + b[tid + 512];
    float* orow = out + (size_t)row * DD;
    orow[tid] = o0; orow[tid + 256] = o1; orow[tid + 512] = o2;
    if (out_r) {
        float* rrow = out_r + (size_t)row * DD;
        rrow[tid]       = to_tf32f(o0);
        rrow[tid + 256] = to_tf32f(o1);
        rrow[tid + 512] = to_tf32f(o2);
    }
}

// ---------------------------------------------------------------------------
extern "C" void kernel_launch(void* const* d_in, const int* in_sizes, int n_in,
                              void* d_out, int out_size) {
    const int*   ids      = (const int*)  d_in[0];
    const float* mask     = (const float*)d_in[2];
    const float* tok_emb  = (const float*)d_in[3];
    const float* pos_emb  = (const float*)d_in[4];
    const float* c_attn_w = (const float*)d_in[5];
    const float* c_attn_b = (const float*)d_in[6];
    const float* c_proj_w = (const float*)d_in[7];
    const float* c_proj_b = (const float*)d_in[8];
    const float* ln1_w    = (const float*)d_in[9];
    const float* ln1_b    = (const float*)d_in[10];
    const float* c_fc_w   = (const float*)d_in[11];
    const float* c_fc_b   = (const float*)d_in[12];
    const float* mlp_w    = (const float*)d_in[13];
    const float* mlp_b    = (const float*)d_in[14];
    const float* ln2_w    = (const float*)d_in[15];
    const float* ln2_b    = (const float*)d_in[16];

    float *h, *hr, *n, *nr, *tmp, *attn, *qkv, *fc;
    float *wta, *wtp, *wtf, *wtm;
    cudaGetSymbolAddress((void**)&h,    g_h);
    cudaGetSymbolAddress((void**)&hr,   g_hr);
    cudaGetSymbolAddress((void**)&n,    g_n);
    cudaGetSymbolAddress((void**)&nr,   g_nr);
    cudaGetSymbolAddress((void**)&tmp,  g_tmp);
    cudaGetSymbolAddress((void**)&attn, g_attn);
    cudaGetSymbolAddress((void**)&qkv,  g_qkv);
    cudaGetSymbolAddress((void**)&fc,   g_fc);
    cudaGetSymbolAddress((void**)&wta,  g_wta);
    cudaGetSymbolAddress((void**)&wtp,  g_wtp);
    cudaGetSymbolAddress((void**)&wtf,  g_wtf);
    cudaGetSymbolAddress((void**)&wtm,  g_wtm);

    const int gemmSmem  = 3 * 2 * 128 * 36 * 4;                        // 110592 B
    const int flashSmem = (128 * FS + 4 * 64 * FS + 1024) * 4;         // 108544 B
    static int s_attr_set = 0;
    if (!s_attr_set) {
        cudaFuncSetAttribute(gemm3<0>, cudaFuncAttributeMaxDynamicSharedMemorySize, gemmSmem);
        cudaFuncSetAttribute(gemm3<1>, cudaFuncAttributeMaxDynamicSharedMemorySize, gemmSmem);
        cudaFuncSetAttribute(gemm3<2>, cudaFuncAttributeMaxDynamicSharedMemorySize, gemmSmem);
        cudaFuncSetAttribute(flash_kernel, cudaFuncAttributeMaxDynamicSharedMemorySize, flashSmem);
        s_attr_set = 1;
    }

    detect_kernel<<<1, 1>>>(ids);
    embed_kernel<<<(TOKENS * DD + 255) / 256, 256>>>(ids, tok_emb, pos_emb, h, hr);

    // one launch for all weight transposes (tf32-rounded)
    transpose_all<<<T_TOTAL, dim3(32, 8)>>>(c_attn_w, wta, c_proj_w, wtp,
                                            c_fc_w, wtf, mlp_w, wtm);

    for (int i = 0; i < NLAYER; i++) {
        // QKV: hr [4096,768] @ Wt [2304,768]^T  (output tf32-rounded for flash)
        gemm3<2><<<dim3(D3 / 128, TOKENS / 128), 256, gemmSmem>>>(
            hr, wta + (size_t)i * DD * D3, c_attn_b + (size_t)i * D3,
            qkv, D3, DD);

        // fused flash attention -> attn (tf32-rounded)
        flash_kernel<<<dim3(SS / 128, NB * HH), 256, flashSmem>>>(qkv, mask, attn);

        // attn out projection
        gemm3<0><<<dim3(DD / 128, TOKENS / 128), 256, gemmSmem>>>(
            attn, wtp + (size_t)i * DD * DD, c_proj_b + (size_t)i * DD,
            tmp, DD, DD);

        // n = LN(h + attn_proj), nr = rna(n)
        add_ln_kernel<<<TOKENS, 256>>>(h, tmp, ln1_w + i * DD, ln1_b + i * DD, n, nr);

        // fc = rna(gelu(nr @ Wfc + b))
        gemm3<1><<<dim3(D4 / 128, TOKENS / 128), 256, gemmSmem>>>(
            nr, wtf + (size_t)i * DD * D4, c_fc_b + (size_t)i * D4,
            fc, D4, DD);

        // m = fc @ Wmlp + b
        gemm3<0><<<dim3(DD / 128, TOKENS / 128), 256, gemmSmem>>>(
            fc, wtm + (size_t)i * D4 * DD, mlp_b + (size_t)i * DD,
            tmp, DD, D4);

        // h = LN(n + m); last layer -> d_out, no rounded copy
        float* dst = (i == NLAYER - 1) ? (float*)d_out : h;
        float* dstr = (i == NLAYER - 1) ? nullptr : hr;
        add_ln_kernel<<<TOKENS, 256>>>(n, tmp, ln2_w + i * DD, ln2_b + i * DD, dst, dstr);
    }
}